// round 7
// baseline (speedup 1.0000x reference)
#include <cuda_runtime.h>
#include <math.h>

#define DIM 1024
#define NQ 4096
#define NKV 4096
#define NH 16
#define HD 64

// ---------------- scratch (device globals; no allocation allowed) ----------
__device__ float g_Q[NQ * DIM];
__device__ float g_K[NKV * DIM];
__device__ float g_V[NKV * DIM];
__device__ float g_AO[NQ * DIM];

// ---------------- helpers ---------------------------------------------------
__device__ __forceinline__ float tf32r(float x) {
    unsigned u;
    asm("cvt.rna.tf32.f32 %0, %1;" : "=r"(u) : "f"(x));
    return __uint_as_float(u);
}
__device__ __forceinline__ unsigned fu(float x) { return __float_as_uint(x); }

__device__ __forceinline__ void mma_tf32(float c[4],
                                         unsigned a0, unsigned a1, unsigned a2, unsigned a3,
                                         unsigned b0, unsigned b1) {
    asm volatile(
        "mma.sync.aligned.m16n8k8.row.col.f32.tf32.tf32.f32 "
        "{%0,%1,%2,%3},{%4,%5,%6,%7},{%8,%9},{%0,%1,%2,%3};"
        : "+f"(c[0]), "+f"(c[1]), "+f"(c[2]), "+f"(c[3])
        : "r"(a0), "r"(a1), "r"(a2), "r"(a3), "r"(b0), "r"(b1));
}

// swizzle selector: {0,1,4,5} keyed by low 2 bits
__device__ __forceinline__ int SIG(int x) { return (x & 1) | ((x & 2) << 1); }

// ---------------- GEMM: C[M,N] = X[M,K] @ W[N,K]^T + b --------------------
// 128x128x32 tiles, 256 threads (8 warps as 4x2), warp tile 32x64.
// smem layout: permuted k-cols: element (row, c) at [row][(c&7)*4 + (c>>3)], width 36.
#define BM 128
#define BN 128
#define BK 32
#define GW 36

__global__ __launch_bounds__(256)
void gemm_tf32(const float* __restrict__ X, const float* __restrict__ W,
               const float* __restrict__ bias, float* __restrict__ C,
               int M, int N, int K) {
    __shared__ float Xs[BM][GW];
    __shared__ float Ws[BN][GW];

    const int tid = threadIdx.x;
    const int warp = tid >> 5, lane = tid & 31;
    const int g = lane >> 2, q = lane & 3;
    const int wm = warp >> 1, wn = warp & 1;          // 4 x 2 warp grid
    const int rowBase = blockIdx.x * BM;
    const int colBase = blockIdx.y * BN;

    float acc[2][8][4];
    #pragma unroll
    for (int i = 0; i < 2; i++)
        #pragma unroll
        for (int j = 0; j < 8; j++)
            #pragma unroll
            for (int v = 0; v < 4; v++) acc[i][j][v] = 0.f;

    for (int k0 = 0; k0 < K; k0 += BK) {
        // stage X, W with permuted layout
        #pragma unroll
        for (int i = 0; i < 4; i++) {
            int idx = tid + i * 256;          // 0..1023
            int r = idx >> 3;                 // 0..127
            int c4 = (idx & 7) << 2;          // 0,4,..28
            int fb = (c4 & 7) * 4 + (c4 >> 3);
            float4 x = *reinterpret_cast<const float4*>(&X[(size_t)(rowBase + r) * K + k0 + c4]);
            Xs[r][fb] = tf32r(x.x); Xs[r][fb + 4] = tf32r(x.y);
            Xs[r][fb + 8] = tf32r(x.z); Xs[r][fb + 12] = tf32r(x.w);
            float4 w = *reinterpret_cast<const float4*>(&W[(size_t)(colBase + r) * K + k0 + c4]);
            Ws[r][fb] = tf32r(w.x); Ws[r][fb + 4] = tf32r(w.y);
            Ws[r][fb + 8] = tf32r(w.z); Ws[r][fb + 12] = tf32r(w.w);
        }
        __syncthreads();

        // vectorized fragment loads: A[i][combo][ks]
        float a[2][4][4];
        #pragma unroll
        for (int i = 0; i < 2; i++) {
            int mr = wm * 32 + i * 16 + g;
            *reinterpret_cast<float4*>(a[i][0]) = *reinterpret_cast<const float4*>(&Xs[mr][q * 4]);
            *reinterpret_cast<float4*>(a[i][1]) = *reinterpret_cast<const float4*>(&Xs[mr + 8][q * 4]);
            *reinterpret_cast<float4*>(a[i][2]) = *reinterpret_cast<const float4*>(&Xs[mr][(q + 4) * 4]);
            *reinterpret_cast<float4*>(a[i][3]) = *reinterpret_cast<const float4*>(&Xs[mr + 8][(q + 4) * 4]);
        }
        #pragma unroll
        for (int j = 0; j < 8; j++) {
            float b[2][4];
            int nr = wn * 64 + 8 * j + g;
            *reinterpret_cast<float4*>(b[0]) = *reinterpret_cast<const float4*>(&Ws[nr][q * 4]);
            *reinterpret_cast<float4*>(b[1]) = *reinterpret_cast<const float4*>(&Ws[nr][(q + 4) * 4]);
            #pragma unroll
            for (int i = 0; i < 2; i++)
                #pragma unroll
                for (int ks = 0; ks < 4; ks++)
                    mma_tf32(acc[i][j], fu(a[i][0][ks]), fu(a[i][1][ks]),
                             fu(a[i][2][ks]), fu(a[i][3][ks]), fu(b[0][ks]), fu(b[1][ks]));
        }
        __syncthreads();
    }

    // epilogue
    #pragma unroll
    for (int i = 0; i < 2; i++) {
        int r0 = rowBase + wm * 32 + i * 16 + g;
        #pragma unroll
        for (int j = 0; j < 8; j++) {
            int col = colBase + wn * 64 + j * 8 + 2 * q;
            float2 bb = *reinterpret_cast<const float2*>(&bias[col]);
            float2 v0 = make_float2(acc[i][j][0] + bb.x, acc[i][j][1] + bb.y);
            float2 v1 = make_float2(acc[i][j][2] + bb.x, acc[i][j][3] + bb.y);
            *reinterpret_cast<float2*>(&C[(size_t)r0 * N + col]) = v0;
            *reinterpret_cast<float2*>(&C[(size_t)(r0 + 8) * N + col]) = v1;
        }
    }
}

// ---------------- Flash attention (tf32 mma, vectorized smem) --------------
// grid (NQ/128, NH), 256 threads (8 warps). Warp w owns q rows 16w..16w+15.
// KsT[k][perm(kv)]  (64x64, swizzled), VsT[n][perm(k)] (64x64, swizzled),
// P slab 128x68 (per-warp-private 16-row slabs).
#define PW 68

__global__ __launch_bounds__(256, 2)
void attn_tf32(const float* __restrict__ Q, const float* __restrict__ K,
               const float* __restrict__ V, float* __restrict__ AO) {
    extern __shared__ float smem[];
    float* Ks = smem;                       // 64 x 64  (rows = k)
    float* Vs = Ks + 64 * 64;               // 64 x 64  (rows = n)
    float* Ps = Vs + 64 * 64;               // 128 x 68

    const int tid = threadIdx.x;
    const int warp = tid >> 5, lane = tid & 31;
    const int g = lane >> 2, q = lane & 3;
    const int h = blockIdx.y;
    const int q0 = blockIdx.x * 128;
    const int colBase = h * HD;
    const int sigq = SIG(q);      // for K frag loads (row&3 == q)
    const int sigg = SIG(g & 3);  // for V frag loads (row&3 == g&3)

    // hoist Q fragments straight from global; fold SCALE*log2(e)
    const float qsc = 0.125f * 1.44269504088896f;
    unsigned qa[8][4];
    {
        const float* Qr0 = Q + (size_t)(q0 + warp * 16 + g) * DIM + colBase;
        const float* Qr1 = Qr0 + (size_t)8 * DIM;
        #pragma unroll
        for (int s = 0; s < 8; s++) {
            qa[s][0] = fu(tf32r(Qr0[8 * s + q] * qsc));
            qa[s][1] = fu(tf32r(Qr1[8 * s + q] * qsc));
            qa[s][2] = fu(tf32r(Qr0[8 * s + q + 4] * qsc));
            qa[s][3] = fu(tf32r(Qr1[8 * s + q + 4] * qsc));
        }
    }

    float ofrag[8][4];
    #pragma unroll
    for (int j = 0; j < 8; j++)
        #pragma unroll
        for (int v = 0; v < 4; v++) ofrag[j][v] = 0.f;
    float m0 = -INFINITY, m1 = -INFINITY, l0 = 0.f, l1 = 0.f;

    float* Pw = Ps + warp * 16 * PW;        // per-warp-private P slab

    for (int kt = 0; kt < NKV / 64; kt++) {
        const int kv0 = kt * 64;
        __syncthreads();   // everyone done reading Ks/Vs from prev iter

        // ---- stage K transposed: KsT[k][ (kv&7)*8 + kv>>3 , swizzled ] ----
        #pragma unroll
        for (int it = 0; it < 4; it++) {
            int slot = tid + it * 256;      // 0..1023
            int k = slot & 63;
            int rem = slot >> 6;            // 0..15
            int gkv = rem & 7;
            int jj = rem >> 3;              // 0..1
            const float* src = K + (size_t)(kv0 + gkv) * DIM + colBase + k;
            float v0 = src[(size_t)(8 * (4 * jj + 0)) * DIM];
            float v1 = src[(size_t)(8 * (4 * jj + 1)) * DIM];
            float v2 = src[(size_t)(8 * (4 * jj + 2)) * DIM];
            float v3 = src[(size_t)(8 * (4 * jj + 3)) * DIM];
            int unit = (2 * gkv + jj) ^ SIG(k & 3);
            float4 st = make_float4(tf32r(v0), tf32r(v1), tf32r(v2), tf32r(v3));
            *reinterpret_cast<float4*>(&Ks[k * 64 + 4 * unit]) = st;
        }
        // ---- stage V transposed: VsT[n][ (k&7)*8 + k>>3 , swizzled ] ------
        #pragma unroll
        for (int it = 0; it < 4; it++) {
            int slot = tid + it * 256;
            int n = slot & 63;
            int rem = slot >> 6;
            int rr = rem & 7;
            int sq = rem >> 3;
            const float* src = V + (size_t)(kv0 + rr) * DIM + colBase + n;
            float v0 = src[(size_t)(8 * (4 * sq + 0)) * DIM];
            float v1 = src[(size_t)(8 * (4 * sq + 1)) * DIM];
            float v2 = src[(size_t)(8 * (4 * sq + 2)) * DIM];
            float v3 = src[(size_t)(8 * (4 * sq + 3)) * DIM];
            int unit = (2 * rr + sq) ^ SIG(n & 3);
            float4 st = make_float4(tf32r(v0), tf32r(v1), tf32r(v2), tf32r(v3));
            *reinterpret_cast<float4*>(&Vs[n * 64 + 4 * unit]) = st;
        }
        __syncthreads();

        // ---- S = Q @ K^T (log2-prescaled) --------------------------------
        float sfrag[8][4];
        #pragma unroll
        for (int j = 0; j < 8; j++)
            #pragma unroll
            for (int v = 0; v < 4; v++) sfrag[j][v] = 0.f;
        #pragma unroll
        for (int s = 0; s < 8; s++) {
            float kb[2][2][4];   // [h=k-half][jj][jl]
            #pragma unroll
            for (int hh = 0; hh < 2; hh++)
                #pragma unroll
                for (int jj = 0; jj < 2; jj++) {
                    int krow = 8 * s + q + 4 * hh;
                    int unit = (2 * g + jj) ^ sigq;
                    *reinterpret_cast<float4*>(kb[hh][jj]) =
                        *reinterpret_cast<const float4*>(&Ks[krow * 64 + 4 * unit]);
                }
            #pragma unroll
            for (int jj = 0; jj < 2; jj++)
                #pragma unroll
                for (int jl = 0; jl < 4; jl++)
                    mma_tf32(sfrag[4 * jj + jl], qa[s][0], qa[s][1], qa[s][2], qa[s][3],
                             fu(kb[0][jj][jl]), fu(kb[1][jj][jl]));
        }

        // ---- online softmax in exp2 domain -------------------------------
        float mx0 = -INFINITY, mx1 = -INFINITY;
        #pragma unroll
        for (int j = 0; j < 8; j++) {
            mx0 = fmaxf(mx0, fmaxf(sfrag[j][0], sfrag[j][1]));
            mx1 = fmaxf(mx1, fmaxf(sfrag[j][2], sfrag[j][3]));
        }
        #pragma unroll
        for (int msk = 1; msk < 4; msk <<= 1) {
            mx0 = fmaxf(mx0, __shfl_xor_sync(0xffffffffu, mx0, msk));
            mx1 = fmaxf(mx1, __shfl_xor_sync(0xffffffffu, mx1, msk));
        }
        float mn0 = fmaxf(m0, mx0), mn1 = fmaxf(m1, mx1);
        float al0 = exp2f(m0 - mn0), al1 = exp2f(m1 - mn1);
        m0 = mn0; m1 = mn1;

        float rs0 = 0.f, rs1 = 0.f;
        #pragma unroll
        for (int j = 0; j < 8; j++) {
            float p0 = exp2f(sfrag[j][0] - mn0);
            float p1 = exp2f(sfrag[j][1] - mn0);
            float p2 = exp2f(sfrag[j][2] - mn1);
            float p3 = exp2f(sfrag[j][3] - mn1);
            sfrag[j][0] = p0; sfrag[j][1] = p1; sfrag[j][2] = p2; sfrag[j][3] = p3;
            rs0 += p0 + p1; rs1 += p2 + p3;
        }
        #pragma unroll
        for (int msk = 1; msk < 4; msk <<= 1) {
            rs0 += __shfl_xor_sync(0xffffffffu, rs0, msk);
            rs1 += __shfl_xor_sync(0xffffffffu, rs1, msk);
        }
        l0 = l0 * al0 + rs0;
        l1 = l1 * al1 + rs1;
        #pragma unroll
        for (int j = 0; j < 8; j++) {
            ofrag[j][0] *= al0; ofrag[j][1] *= al0;
            ofrag[j][2] *= al1; ofrag[j][3] *= al1;
        }

        // ---- P -> per-warp smem (permuted layout, vectorized) -------------
        #pragma unroll
        for (int b = 0; b < 2; b++)
            #pragma unroll
            for (int jj = 0; jj < 2; jj++) {
                float4 v0 = make_float4(tf32r(sfrag[4 * jj + 0][b]), tf32r(sfrag[4 * jj + 1][b]),
                                        tf32r(sfrag[4 * jj + 2][b]), tf32r(sfrag[4 * jj + 3][b]));
                *reinterpret_cast<float4*>(&Pw[g * PW + (2 * q + b) * 8 + 4 * jj]) = v0;
                float4 v1 = make_float4(tf32r(sfrag[4 * jj + 0][2 + b]), tf32r(sfrag[4 * jj + 1][2 + b]),
                                        tf32r(sfrag[4 * jj + 2][2 + b]), tf32r(sfrag[4 * jj + 3][2 + b]));
                *reinterpret_cast<float4*>(&Pw[(g + 8) * PW + (2 * q + b) * 8 + 4 * jj]) = v1;
            }
        __syncwarp();

        // ---- A fragments of P (vectorized) --------------------------------
        float pa[2][2][8];   // [rowhalf][rtophalf][s]
        #pragma unroll
        for (int rh = 0; rh < 2; rh++)
            #pragma unroll
            for (int hh = 0; hh < 2; hh++) {
                int row = g + 8 * rh;
                int rtop = q + 4 * hh;
                *reinterpret_cast<float4*>(&pa[rh][hh][0]) =
                    *reinterpret_cast<const float4*>(&Pw[row * PW + rtop * 8 + 0]);
                *reinterpret_cast<float4*>(&pa[rh][hh][4]) =
                    *reinterpret_cast<const float4*>(&Pw[row * PW + rtop * 8 + 4]);
            }

        // ---- O += P @ V ---------------------------------------------------
        #pragma unroll
        for (int j = 0; j < 8; j++) {
            float vb[2][8];  // [h=k-half][s]
            int nrow = 8 * j + g;
            #pragma unroll
            for (int hh = 0; hh < 2; hh++) {
                int rr = q + 4 * hh;
                *reinterpret_cast<float4*>(&vb[hh][0]) =
                    *reinterpret_cast<const float4*>(&Vs[nrow * 64 + 4 * ((2 * rr + 0) ^ sigg)]);
                *reinterpret_cast<float4*>(&vb[hh][4]) =
                    *reinterpret_cast<const float4*>(&Vs[nrow * 64 + 4 * ((2 * rr + 1) ^ sigg)]);
            }
            #pragma unroll
            for (int s = 0; s < 8; s++)
                mma_tf32(ofrag[j], fu(pa[0][0][s]), fu(pa[1][0][s]),
                         fu(pa[0][1][s]), fu(pa[1][1][s]), fu(vb[0][s]), fu(vb[1][s]));
        }
    }

    // normalize + write
    float inv0 = 1.f / l0, inv1 = 1.f / l1;
    int r0 = q0 + warp * 16 + g;
    #pragma unroll
    for (int j = 0; j < 8; j++) {
        int col = colBase + 8 * j + 2 * q;
        *reinterpret_cast<float2*>(&AO[(size_t)r0 * DIM + col]) =
            make_float2(ofrag[j][0] * inv0, ofrag[j][1] * inv0);
        *reinterpret_cast<float2*>(&AO[(size_t)(r0 + 8) * DIM + col]) =
            make_float2(ofrag[j][2] * inv1, ofrag[j][3] * inv1);
    }
}

// ---------------- launch ---------------------------------------------------
extern "C" void kernel_launch(void* const* d_in, const int* in_sizes, int n_in,
                              void* d_out, int out_size) {
    const float* q   = (const float*)d_in[0];
    const float* kv  = (const float*)d_in[1];
    const float* q_w = (const float*)d_in[2];
    const float* q_b = (const float*)d_in[3];
    const float* k_w = (const float*)d_in[4];
    const float* k_b = (const float*)d_in[5];
    const float* v_w = (const float*)d_in[6];
    const float* v_b = (const float*)d_in[7];
    const float* o_w = (const float*)d_in[8];
    const float* o_b = (const float*)d_in[9];
    float* out = (float*)d_out;

    float *Q, *K, *V, *AO;
    cudaGetSymbolAddress((void**)&Q,  g_Q);
    cudaGetSymbolAddress((void**)&K,  g_K);
    cudaGetSymbolAddress((void**)&V,  g_V);
    cudaGetSymbolAddress((void**)&AO, g_AO);

    dim3 gGrid(NQ / BM, DIM / BN);  // 32 x 8
    gemm_tf32<<<gGrid, 256>>>(q,  q_w, q_b, Q, NQ,  DIM, DIM);
    gemm_tf32<<<gGrid, 256>>>(kv, k_w, k_b, K, NKV, DIM, DIM);
    gemm_tf32<<<gGrid, 256>>>(kv, v_w, v_b, V, NKV, DIM, DIM);

    const size_t attnSmem = (size_t)(64 * 64 + 64 * 64 + 128 * PW) * sizeof(float);
    cudaFuncSetAttribute(attn_tf32, cudaFuncAttributeMaxDynamicSharedMemorySize,
                         (int)attnSmem);
    dim3 aGrid(NQ / 128, NH);       // 32 x 16
    attn_tf32<<<aGrid, 256, attnSmem>>>(Q, K, V, AO);

    gemm_tf32<<<gGrid, 256>>>(AO, o_w, o_b, out, NQ, DIM, DIM);
}

// round 9
// speedup vs baseline: 1.5601x; 1.5601x over previous
#include <cuda_runtime.h>
#include <math.h>

#define DIM 1024
#define NQ 4096
#define NKV 4096
#define NH 16
#define HD 64

// ---------------- scratch (device globals; no allocation allowed) ----------
__device__ float g_Q[NQ * DIM];
__device__ float g_K[NKV * DIM];
__device__ float g_V[NKV * DIM];
__device__ float g_AO[NQ * DIM];

// ---------------- helpers ---------------------------------------------------
__device__ __forceinline__ float tf32r(float x) {
    unsigned u;
    asm("cvt.rna.tf32.f32 %0, %1;" : "=r"(u) : "f"(x));
    return __uint_as_float(u);
}
__device__ __forceinline__ unsigned fu(float x) { return __float_as_uint(x); }

__device__ __forceinline__ void mma_tf32(float c[4],
                                         unsigned a0, unsigned a1, unsigned a2, unsigned a3,
                                         unsigned b0, unsigned b1) {
    asm volatile(
        "mma.sync.aligned.m16n8k8.row.col.f32.tf32.tf32.f32 "
        "{%0,%1,%2,%3},{%4,%5,%6,%7},{%8,%9},{%0,%1,%2,%3};"
        : "+f"(c[0]), "+f"(c[1]), "+f"(c[2]), "+f"(c[3])
        : "r"(a0), "r"(a1), "r"(a2), "r"(a3), "r"(b0), "r"(b1));
}

// ---------------- GEMM: C[M,N] = X[M,K] @ W[N,K]^T + b  (R4 baseline) -----
#define BM 128
#define BN 128
#define BK 32
#define GP 36   // smem row pad

__global__ __launch_bounds__(256)
void gemm_tf32(const float* __restrict__ X, const float* __restrict__ W,
               const float* __restrict__ bias, float* __restrict__ C,
               int M, int N, int K) {
    __shared__ float Xs[BM][GP];
    __shared__ float Ws[BN][GP];

    const int tid = threadIdx.x;
    const int warp = tid >> 5, lane = tid & 31;
    const int g = lane >> 2, q = lane & 3;
    const int wm = warp >> 1, wn = warp & 1;          // 4 x 2 warp grid
    const int rowBase = blockIdx.x * BM;
    const int colBase = blockIdx.y * BN;

    float acc[2][8][4];
    #pragma unroll
    for (int i = 0; i < 2; i++)
        #pragma unroll
        for (int j = 0; j < 8; j++)
            #pragma unroll
            for (int v = 0; v < 4; v++) acc[i][j][v] = 0.f;

    for (int k0 = 0; k0 < K; k0 += BK) {
        #pragma unroll
        for (int i = 0; i < 4; i++) {
            int idx = tid + i * 256;          // 0..1023
            int r = idx >> 3;                 // 0..127
            int c4 = (idx & 7) << 2;          // 0,4,..28
            float4 x = *reinterpret_cast<const float4*>(&X[(size_t)(rowBase + r) * K + k0 + c4]);
            Xs[r][c4 + 0] = tf32r(x.x); Xs[r][c4 + 1] = tf32r(x.y);
            Xs[r][c4 + 2] = tf32r(x.z); Xs[r][c4 + 3] = tf32r(x.w);
            float4 w = *reinterpret_cast<const float4*>(&W[(size_t)(colBase + r) * K + k0 + c4]);
            Ws[r][c4 + 0] = tf32r(w.x); Ws[r][c4 + 1] = tf32r(w.y);
            Ws[r][c4 + 2] = tf32r(w.z); Ws[r][c4 + 3] = tf32r(w.w);
        }
        __syncthreads();

        #pragma unroll
        for (int ks = 0; ks < 4; ks++) {
            const int kk = ks * 8;
            unsigned b0[8], b1[8];
            #pragma unroll
            for (int j = 0; j < 8; j++) {
                b0[j] = fu(Ws[wn * 64 + j * 8 + g][kk + q]);
                b1[j] = fu(Ws[wn * 64 + j * 8 + g][kk + q + 4]);
            }
            #pragma unroll
            for (int i = 0; i < 2; i++) {
                int mr = wm * 32 + i * 16 + g;
                unsigned a0 = fu(Xs[mr][kk + q]);
                unsigned a1 = fu(Xs[mr + 8][kk + q]);
                unsigned a2 = fu(Xs[mr][kk + q + 4]);
                unsigned a3 = fu(Xs[mr + 8][kk + q + 4]);
                #pragma unroll
                for (int j = 0; j < 8; j++)
                    mma_tf32(acc[i][j], a0, a1, a2, a3, b0[j], b1[j]);
            }
        }
        __syncthreads();
    }

    #pragma unroll
    for (int i = 0; i < 2; i++) {
        int r0 = rowBase + wm * 32 + i * 16 + g;
        #pragma unroll
        for (int j = 0; j < 8; j++) {
            int col = colBase + wn * 64 + j * 8 + 2 * q;
            float2 bb = *reinterpret_cast<const float2*>(&bias[col]);
            float2 v0 = make_float2(acc[i][j][0] + bb.x, acc[i][j][1] + bb.y);
            float2 v1 = make_float2(acc[i][j][2] + bb.x, acc[i][j][3] + bb.y);
            *reinterpret_cast<float2*>(&C[(size_t)r0 * N + col]) = v0;
            *reinterpret_cast<float2*>(&C[(size_t)(r0 + 8) * N + col]) = v1;
        }
    }
}

// ---------------- Flash attention (tf32 mma, 32 q-rows per warp) -----------
// grid (NQ/128, NH), 128 threads (4 warps). Warp w owns q rows 32w..32w+31.
// K fragments loaded once per k-slice feed BOTH 16-row halves (2x reuse).
#define KPAD 68
#define VPAD 72
#define PPAD 76

__global__ __launch_bounds__(128)
void attn_tf32(const float* __restrict__ Q, const float* __restrict__ K,
               const float* __restrict__ V, float* __restrict__ AO) {
    extern __shared__ float smem[];
    float* Ks = smem;                       // 64 x 68
    float* Vs = Ks + 64 * KPAD;             // 64 x 72
    float* Ps = Vs + 64 * VPAD;             // 128 x 76

    const int tid = threadIdx.x;
    const int warp = tid >> 5, lane = tid & 31;
    const int g = lane >> 2, q = lane & 3;
    const int h = blockIdx.y;
    const int q0 = blockIdx.x * 128;
    const int colBase = h * HD;

    // hoist Q fragments straight from global; fold SCALE*log2(e)
    const float qsc = 0.125f * 1.44269504088896f;
    unsigned qa[8][8];   // [s][0..3]=rows g,g+8 | [4..7]=rows g+16,g+24
    {
        const float* Qr0 = Q + (size_t)(q0 + warp * 32 + g) * DIM + colBase;
        const float* Qr1 = Qr0 + (size_t)8 * DIM;
        const float* Qr2 = Qr0 + (size_t)16 * DIM;
        const float* Qr3 = Qr0 + (size_t)24 * DIM;
        #pragma unroll
        for (int s = 0; s < 8; s++) {
            qa[s][0] = fu(tf32r(Qr0[8 * s + q] * qsc));
            qa[s][1] = fu(tf32r(Qr1[8 * s + q] * qsc));
            qa[s][2] = fu(tf32r(Qr0[8 * s + q + 4] * qsc));
            qa[s][3] = fu(tf32r(Qr1[8 * s + q + 4] * qsc));
            qa[s][4] = fu(tf32r(Qr2[8 * s + q] * qsc));
            qa[s][5] = fu(tf32r(Qr3[8 * s + q] * qsc));
            qa[s][6] = fu(tf32r(Qr2[8 * s + q + 4] * qsc));
            qa[s][7] = fu(tf32r(Qr3[8 * s + q + 4] * qsc));
        }
    }

    float oA[8][4], oB[8][4];
    #pragma unroll
    for (int j = 0; j < 8; j++)
        #pragma unroll
        for (int v = 0; v < 4; v++) { oA[j][v] = 0.f; oB[j][v] = 0.f; }
    float m0 = -INFINITY, m1 = -INFINITY, m2 = -INFINITY, m3 = -INFINITY;
    float l0 = 0.f, l1 = 0.f, l2 = 0.f, l3 = 0.f;

    float* Pw = Ps + warp * 32 * PPAD;      // per-warp-private 32-row P slab

    for (int kt = 0; kt < NKV / 64; kt++) {
        const int kv0 = kt * 64;
        __syncthreads();   // everyone done reading Ks/Vs from prev iter
        // stage K, V tiles (64 x 64 each), 128 threads
        #pragma unroll
        for (int i = 0; i < 8; i++) {
            int idx = tid + i * 128;        // 0..1023
            int r = idx >> 4;               // 0..63
            int c4 = (idx & 15) << 2;
            float4 kv4 = *reinterpret_cast<const float4*>(&K[(size_t)(kv0 + r) * DIM + colBase + c4]);
            float* kd = &Ks[r * KPAD + c4];
            kd[0] = tf32r(kv4.x); kd[1] = tf32r(kv4.y);
            kd[2] = tf32r(kv4.z); kd[3] = tf32r(kv4.w);
            float4 vv4 = *reinterpret_cast<const float4*>(&V[(size_t)(kv0 + r) * DIM + colBase + c4]);
            float* vd = &Vs[r * VPAD + c4];
            vd[0] = tf32r(vv4.x); vd[1] = tf32r(vv4.y);
            vd[2] = tf32r(vv4.z); vd[3] = tf32r(vv4.w);
        }
        __syncthreads();

        // ---- S = Q @ K^T : both 16-row halves share each K fragment ------
        float sA[8][4], sB[8][4];
        #pragma unroll
        for (int j = 0; j < 8; j++)
            #pragma unroll
            for (int v = 0; v < 4; v++) { sA[j][v] = 0.f; sB[j][v] = 0.f; }
        #pragma unroll
        for (int s = 0; s < 8; s++) {
            unsigned b0[8], b1[8];
            #pragma unroll
            for (int j = 0; j < 8; j++) {
                b0[j] = fu(Ks[(8 * j + g) * KPAD + 8 * s + q]);
                b1[j] = fu(Ks[(8 * j + g) * KPAD + 8 * s + q + 4]);
            }
            #pragma unroll
            for (int j = 0; j < 8; j++) {
                mma_tf32(sA[j], qa[s][0], qa[s][1], qa[s][2], qa[s][3], b0[j], b1[j]);
                mma_tf32(sB[j], qa[s][4], qa[s][5], qa[s][6], qa[s][7], b0[j], b1[j]);
            }
        }

        // ---- online softmax, exp2 domain (4 row-groups per lane) ---------
        float mxa0 = -INFINITY, mxa1 = -INFINITY, mxb0 = -INFINITY, mxb1 = -INFINITY;
        #pragma unroll
        for (int j = 0; j < 8; j++) {
            mxa0 = fmaxf(mxa0, fmaxf(sA[j][0], sA[j][1]));
            mxa1 = fmaxf(mxa1, fmaxf(sA[j][2], sA[j][3]));
            mxb0 = fmaxf(mxb0, fmaxf(sB[j][0], sB[j][1]));
            mxb1 = fmaxf(mxb1, fmaxf(sB[j][2], sB[j][3]));
        }
        #pragma unroll
        for (int msk = 1; msk < 4; msk <<= 1) {
            mxa0 = fmaxf(mxa0, __shfl_xor_sync(0xffffffffu, mxa0, msk));
            mxa1 = fmaxf(mxa1, __shfl_xor_sync(0xffffffffu, mxa1, msk));
            mxb0 = fmaxf(mxb0, __shfl_xor_sync(0xffffffffu, mxb0, msk));
            mxb1 = fmaxf(mxb1, __shfl_xor_sync(0xffffffffu, mxb1, msk));
        }
        float mn0 = fmaxf(m0, mxa0), mn1 = fmaxf(m1, mxa1);
        float mn2 = fmaxf(m2, mxb0), mn3 = fmaxf(m3, mxb1);
        float al0 = exp2f(m0 - mn0), al1 = exp2f(m1 - mn1);
        float al2 = exp2f(m2 - mn2), al3 = exp2f(m3 - mn3);
        m0 = mn0; m1 = mn1; m2 = mn2; m3 = mn3;

        float rs0 = 0.f, rs1 = 0.f, rs2 = 0.f, rs3 = 0.f;
        #pragma unroll
        for (int j = 0; j < 8; j++) {
            float p0 = exp2f(sA[j][0] - mn0);
            float p1 = exp2f(sA[j][1] - mn0);
            float p2 = exp2f(sA[j][2] - mn1);
            float p3 = exp2f(sA[j][3] - mn1);
            sA[j][0] = p0; sA[j][1] = p1; sA[j][2] = p2; sA[j][3] = p3;
            rs0 += p0 + p1; rs1 += p2 + p3;
            float r0v = exp2f(sB[j][0] - mn2);
            float r1v = exp2f(sB[j][1] - mn2);
            float r2v = exp2f(sB[j][2] - mn3);
            float r3v = exp2f(sB[j][3] - mn3);
            sB[j][0] = r0v; sB[j][1] = r1v; sB[j][2] = r2v; sB[j][3] = r3v;
            rs2 += r0v + r1v; rs3 += r2v + r3v;
        }
        #pragma unroll
        for (int msk = 1; msk < 4; msk <<= 1) {
            rs0 += __shfl_xor_sync(0xffffffffu, rs0, msk);
            rs1 += __shfl_xor_sync(0xffffffffu, rs1, msk);
            rs2 += __shfl_xor_sync(0xffffffffu, rs2, msk);
            rs3 += __shfl_xor_sync(0xffffffffu, rs3, msk);
        }
        l0 = l0 * al0 + rs0; l1 = l1 * al1 + rs1;
        l2 = l2 * al2 + rs2; l3 = l3 * al3 + rs3;
        #pragma unroll
        for (int j = 0; j < 8; j++) {
            oA[j][0] *= al0; oA[j][1] *= al0; oA[j][2] *= al1; oA[j][3] *= al1;
            oB[j][0] *= al2; oB[j][1] *= al2; oB[j][2] *= al3; oB[j][3] *= al3;
        }

        // ---- P -> per-warp smem slab (tf32) ------------------------------
        #pragma unroll
        for (int j = 0; j < 8; j++) {
            int col = 8 * j + 2 * q;
            *reinterpret_cast<float2*>(&Pw[g * PPAD + col]) =
                make_float2(tf32r(sA[j][0]), tf32r(sA[j][1]));
            *reinterpret_cast<float2*>(&Pw[(g + 8) * PPAD + col]) =
                make_float2(tf32r(sA[j][2]), tf32r(sA[j][3]));
            *reinterpret_cast<float2*>(&Pw[(g + 16) * PPAD + col]) =
                make_float2(tf32r(sB[j][0]), tf32r(sB[j][1]));
            *reinterpret_cast<float2*>(&Pw[(g + 24) * PPAD + col]) =
                make_float2(tf32r(sB[j][2]), tf32r(sB[j][3]));
        }
        __syncwarp();

        // ---- O += P @ V : V fragments shared by both halves --------------
        #pragma unroll
        for (int s = 0; s < 8; s++) {
            unsigned a0 = fu(Pw[g * PPAD + 8 * s + q]);
            unsigned a1 = fu(Pw[(g + 8) * PPAD + 8 * s + q]);
            unsigned a2 = fu(Pw[g * PPAD + 8 * s + q + 4]);
            unsigned a3 = fu(Pw[(g + 8) * PPAD + 8 * s + q + 4]);
            unsigned c0 = fu(Pw[(g + 16) * PPAD + 8 * s + q]);
            unsigned c1 = fu(Pw[(g + 24) * PPAD + 8 * s + q]);
            unsigned c2 = fu(Pw[(g + 16) * PPAD + 8 * s + q + 4]);
            unsigned c3 = fu(Pw[(g + 24) * PPAD + 8 * s + q + 4]);
            unsigned b0[8], b1[8];
            #pragma unroll
            for (int j = 0; j < 8; j++) {
                b0[j] = fu(Vs[(8 * s + q) * VPAD + 8 * j + g]);
                b1[j] = fu(Vs[(8 * s + q + 4) * VPAD + 8 * j + g]);
            }
            #pragma unroll
            for (int j = 0; j < 8; j++) {
                mma_tf32(oA[j], a0, a1, a2, a3, b0[j], b1[j]);
                mma_tf32(oB[j], c0, c1, c2, c3, b0[j], b1[j]);
            }
        }
    }

    // normalize + write (4 row-groups)
    float inv0 = 1.f / l0, inv1 = 1.f / l1, inv2 = 1.f / l2, inv3 = 1.f / l3;
    int r0 = q0 + warp * 32 + g;
    #pragma unroll
    for (int j = 0; j < 8; j++) {
        int col = colBase + 8 * j + 2 * q;
        *reinterpret_cast<float2*>(&AO[(size_t)r0 * DIM + col]) =
            make_float2(oA[j][0] * inv0, oA[j][1] * inv0);
        *reinterpret_cast<float2*>(&AO[(size_t)(r0 + 8) * DIM + col]) =
            make_float2(oA[j][2] * inv1, oA[j][3] * inv1);
        *reinterpret_cast<float2*>(&AO[(size_t)(r0 + 16) * DIM + col]) =
            make_float2(oB[j][0] * inv2, oB[j][1] * inv2);
        *reinterpret_cast<float2*>(&AO[(size_t)(r0 + 24) * DIM + col]) =
            make_float2(oB[j][2] * inv3, oB[j][3] * inv3);
    }
}

// ---------------- launch ---------------------------------------------------
extern "C" void kernel_launch(void* const* d_in, const int* in_sizes, int n_in,
                              void* d_out, int out_size) {
    const float* q   = (const float*)d_in[0];
    const float* kv  = (const float*)d_in[1];
    const float* q_w = (const float*)d_in[2];
    const float* q_b = (const float*)d_in[3];
    const float* k_w = (const float*)d_in[4];
    const float* k_b = (const float*)d_in[5];
    const float* v_w = (const float*)d_in[6];
    const float* v_b = (const float*)d_in[7];
    const float* o_w = (const float*)d_in[8];
    const float* o_b = (const float*)d_in[9];
    float* out = (float*)d_out;

    float *Q, *K, *V, *AO;
    cudaGetSymbolAddress((void**)&Q,  g_Q);
    cudaGetSymbolAddress((void**)&K,  g_K);
    cudaGetSymbolAddress((void**)&V,  g_V);
    cudaGetSymbolAddress((void**)&AO, g_AO);

    dim3 gGrid(NQ / BM, DIM / BN);  // 32 x 8
    gemm_tf32<<<gGrid, 256>>>(q,  q_w, q_b, Q, NQ,  DIM, DIM);
    gemm_tf32<<<gGrid, 256>>>(kv, k_w, k_b, K, NKV, DIM, DIM);
    gemm_tf32<<<gGrid, 256>>>(kv, v_w, v_b, V, NKV, DIM, DIM);

    const size_t attnSmem = (size_t)(64 * KPAD + 64 * VPAD + 128 * PPAD) * sizeof(float);
    cudaFuncSetAttribute(attn_tf32, cudaFuncAttributeMaxDynamicSharedMemorySize,
                         (int)attnSmem);
    dim3 aGrid(NQ / 128, NH);       // 32 x 16
    attn_tf32<<<aGrid, 128, attnSmem>>>(Q, K, V, AO);

    gemm_tf32<<<gGrid, 256>>>(AO, o_w, o_b, out, NQ, DIM, DIM);
}

// round 10
// speedup vs baseline: 1.6504x; 1.0579x over previous
#include <cuda_runtime.h>
#include <math.h>

#define DIM 1024
#define NQ 4096
#define NKV 4096
#define NH 16
#define HD 64

// ---------------- scratch (device globals; no allocation allowed) ----------
__device__ float g_Q[NQ * DIM];
__device__ float g_K[NKV * DIM];
__device__ float g_V[NKV * DIM];
__device__ float g_AO[NQ * DIM];
__device__ float g_X[NQ * DIM];     // tf32-rounded q input
__device__ float g_KV[NKV * DIM];   // tf32-rounded kv input
__device__ float g_Wq[DIM * DIM];
__device__ float g_Wk[DIM * DIM];
__device__ float g_Wv[DIM * DIM];
__device__ float g_Wo[DIM * DIM];

// ---------------- helpers ---------------------------------------------------
__device__ __forceinline__ float tf32r(float x) {
    unsigned u;
    asm("cvt.rna.tf32.f32 %0, %1;" : "=r"(u) : "f"(x));
    return __uint_as_float(u);
}
__device__ __forceinline__ unsigned fu(float x) { return __float_as_uint(x); }

__device__ __forceinline__ void mma_tf32(float c[4],
                                         unsigned a0, unsigned a1, unsigned a2, unsigned a3,
                                         unsigned b0, unsigned b1) {
    asm volatile(
        "mma.sync.aligned.m16n8k8.row.col.f32.tf32.tf32.f32 "
        "{%0,%1,%2,%3},{%4,%5,%6,%7},{%8,%9},{%0,%1,%2,%3};"
        : "+f"(c[0]), "+f"(c[1]), "+f"(c[2]), "+f"(c[3])
        : "r"(a0), "r"(a1), "r"(a2), "r"(a3), "r"(b0), "r"(b1));
}

__device__ __forceinline__ unsigned saddr(const void* p) {
    return (unsigned)__cvta_generic_to_shared(p);
}
__device__ __forceinline__ void cpa16(unsigned dst, const float* src) {
    asm volatile("cp.async.cg.shared.global [%0], [%1], 16;" :: "r"(dst), "l"(src));
}
__device__ __forceinline__ void cpa_commit() {
    asm volatile("cp.async.commit_group;");
}
template <int N> __device__ __forceinline__ void cpa_wait() {
    asm volatile("cp.async.wait_group %0;" :: "n"(N));
}

// ---------------- pre-round pass: dst = tf32r(src) -------------------------
__global__ __launch_bounds__(256)
void round4_kernel(const float4* __restrict__ src, float4* __restrict__ dst, int n4) {
    int i = blockIdx.x * blockDim.x + threadIdx.x;
    if (i < n4) {
        float4 v = src[i];
        dst[i] = make_float4(tf32r(v.x), tf32r(v.y), tf32r(v.z), tf32r(v.w));
    }
}

// ---------------- GEMM: C[M,N] = X[M,K] @ W[N,K]^T + b ---------------------
// inputs pre-rounded to tf32; cp.async double-buffered pipeline.
#define BM 128
#define BN 128
#define BK 32
#define GP 36   // smem row pad

#define GEMM_SMEM ((2 * BM * GP + 2 * BN * GP) * 4)

__global__ __launch_bounds__(256, 2)
void gemm_tf32(const float* __restrict__ X, const float* __restrict__ W,
               const float* __restrict__ bias, float* __restrict__ C,
               int M, int N, int K, int roundOut) {
    extern __shared__ float gs[];
    // layout: Xs[2][BM][GP], Ws[2][BN][GP]
    const int tid = threadIdx.x;
    const int warp = tid >> 5, lane = tid & 31;
    const int g = lane >> 2, q = lane & 3;
    const int wm = warp >> 1, wn = warp & 1;          // 4 x 2 warp grid
    const int rowBase = blockIdx.x * BM;
    const int colBase = blockIdx.y * BN;
    const int NT = K / BK;

    float acc[2][8][4];
    #pragma unroll
    for (int i = 0; i < 2; i++)
        #pragma unroll
        for (int j = 0; j < 8; j++)
            #pragma unroll
            for (int v = 0; v < 4; v++) acc[i][j][v] = 0.f;

    // prologue: stage tile 0 into buffer 0
    {
        #pragma unroll
        for (int i = 0; i < 4; i++) {
            int idx = tid + i * 256;          // 0..1023
            int r = idx >> 3;                 // 0..127
            int c4 = (idx & 7) << 2;          // 0,4,..28
            cpa16(saddr(&gs[0 * BM * GP + r * GP + c4]),
                  &X[(size_t)(rowBase + r) * K + c4]);
            cpa16(saddr(&gs[2 * BM * GP + 0 * BN * GP + r * GP + c4]),
                  &W[(size_t)(colBase + r) * K + c4]);
        }
        cpa_commit();
    }

    for (int kt = 0; kt < NT; kt++) {
        __syncthreads();   // prior readers of the buffer we are about to fill are done
        if (kt + 1 < NT) {
            int k0 = (kt + 1) * BK;
            int buf = (kt + 1) & 1;
            #pragma unroll
            for (int i = 0; i < 4; i++) {
                int idx = tid + i * 256;
                int r = idx >> 3;
                int c4 = (idx & 7) << 2;
                cpa16(saddr(&gs[buf * BM * GP + r * GP + c4]),
                      &X[(size_t)(rowBase + r) * K + k0 + c4]);
                cpa16(saddr(&gs[2 * BM * GP + buf * BN * GP + r * GP + c4]),
                      &W[(size_t)(colBase + r) * K + k0 + c4]);
            }
            cpa_commit();
            cpa_wait<1>();
        } else {
            cpa_wait<0>();
        }
        __syncthreads();   // tile kt visible

        const float* Xs = gs + (kt & 1) * BM * GP;
        const float* Ws = gs + 2 * BM * GP + (kt & 1) * BN * GP;

        #pragma unroll
        for (int ks = 0; ks < 4; ks++) {
            const int kk = ks * 8;
            unsigned b0[8], b1[8];
            #pragma unroll
            for (int j = 0; j < 8; j++) {
                b0[j] = fu(Ws[(wn * 64 + j * 8 + g) * GP + kk + q]);
                b1[j] = fu(Ws[(wn * 64 + j * 8 + g) * GP + kk + q + 4]);
            }
            #pragma unroll
            for (int i = 0; i < 2; i++) {
                int mr = wm * 32 + i * 16 + g;
                unsigned a0 = fu(Xs[mr * GP + kk + q]);
                unsigned a1 = fu(Xs[(mr + 8) * GP + kk + q]);
                unsigned a2 = fu(Xs[mr * GP + kk + q + 4]);
                unsigned a3 = fu(Xs[(mr + 8) * GP + kk + q + 4]);
                #pragma unroll
                for (int j = 0; j < 8; j++)
                    mma_tf32(acc[i][j], a0, a1, a2, a3, b0[j], b1[j]);
            }
        }
    }

    #pragma unroll
    for (int i = 0; i < 2; i++) {
        int r0 = rowBase + wm * 32 + i * 16 + g;
        #pragma unroll
        for (int j = 0; j < 8; j++) {
            int col = colBase + wn * 64 + j * 8 + 2 * q;
            float2 bb = *reinterpret_cast<const float2*>(&bias[col]);
            float2 v0 = make_float2(acc[i][j][0] + bb.x, acc[i][j][1] + bb.y);
            float2 v1 = make_float2(acc[i][j][2] + bb.x, acc[i][j][3] + bb.y);
            if (roundOut) {
                v0.x = tf32r(v0.x); v0.y = tf32r(v0.y);
                v1.x = tf32r(v1.x); v1.y = tf32r(v1.y);
            }
            *reinterpret_cast<float2*>(&C[(size_t)r0 * N + col]) = v0;
            *reinterpret_cast<float2*>(&C[(size_t)(r0 + 8) * N + col]) = v1;
        }
    }
}

// ---------------- Flash attention (tf32 mma, 32 q-rows/warp, cp.async) -----
// grid (NQ/128, NH), 128 threads (4 warps). Warp w owns q rows 32w..32w+31.
// K/V double-buffered via cp.async (values pre-rounded by projection GEMMs).
#define KPAD 68
#define VPAD 72
#define PPAD 76
#define KVSZ (64 * KPAD + 64 * VPAD)   // floats per K/V buffer

__global__ __launch_bounds__(128, 2)
void attn_tf32(const float* __restrict__ Q, const float* __restrict__ K,
               const float* __restrict__ V, float* __restrict__ AO) {
    extern __shared__ float smem[];
    float* Ps = smem + 2 * KVSZ;            // 128 x 76

    const int tid = threadIdx.x;
    const int warp = tid >> 5, lane = tid & 31;
    const int g = lane >> 2, q = lane & 3;
    const int h = blockIdx.y;
    const int q0 = blockIdx.x * 128;
    const int colBase = h * HD;
    const int NT = NKV / 64;

    // hoist Q fragments straight from global; fold SCALE*log2(e)
    const float qsc = 0.125f * 1.44269504088896f;
    unsigned qa[8][8];   // [s][0..3]=rows g,g+8 | [4..7]=rows g+16,g+24
    {
        const float* Qr0 = Q + (size_t)(q0 + warp * 32 + g) * DIM + colBase;
        const float* Qr1 = Qr0 + (size_t)8 * DIM;
        const float* Qr2 = Qr0 + (size_t)16 * DIM;
        const float* Qr3 = Qr0 + (size_t)24 * DIM;
        #pragma unroll
        for (int s = 0; s < 8; s++) {
            qa[s][0] = fu(tf32r(Qr0[8 * s + q] * qsc));
            qa[s][1] = fu(tf32r(Qr1[8 * s + q] * qsc));
            qa[s][2] = fu(tf32r(Qr0[8 * s + q + 4] * qsc));
            qa[s][3] = fu(tf32r(Qr1[8 * s + q + 4] * qsc));
            qa[s][4] = fu(tf32r(Qr2[8 * s + q] * qsc));
            qa[s][5] = fu(tf32r(Qr3[8 * s + q] * qsc));
            qa[s][6] = fu(tf32r(Qr2[8 * s + q + 4] * qsc));
            qa[s][7] = fu(tf32r(Qr3[8 * s + q + 4] * qsc));
        }
    }

    float oA[8][4], oB[8][4];
    #pragma unroll
    for (int j = 0; j < 8; j++)
        #pragma unroll
        for (int v = 0; v < 4; v++) { oA[j][v] = 0.f; oB[j][v] = 0.f; }
    float m0 = -INFINITY, m1 = -INFINITY, m2 = -INFINITY, m3 = -INFINITY;
    float l0 = 0.f, l1 = 0.f, l2 = 0.f, l3 = 0.f;

    float* Pw = Ps + warp * 32 * PPAD;      // per-warp-private 32-row P slab

    // prologue: stage tile 0 into buffer 0
    {
        #pragma unroll
        for (int i = 0; i < 8; i++) {
            int idx = tid + i * 128;        // 0..1023
            int r = idx >> 4;               // 0..63
            int c4 = (idx & 15) << 2;
            cpa16(saddr(&smem[r * KPAD + c4]),
                  &K[(size_t)r * DIM + colBase + c4]);
            cpa16(saddr(&smem[64 * KPAD + r * VPAD + c4]),
                  &V[(size_t)r * DIM + colBase + c4]);
        }
        cpa_commit();
    }

    for (int kt = 0; kt < NT; kt++) {
        __syncthreads();   // prior readers of buffer (kt+1)&1 done
        if (kt + 1 < NT) {
            int kv0 = (kt + 1) * 64;
            float* Kb = smem + ((kt + 1) & 1) * KVSZ;
            float* Vb = Kb + 64 * KPAD;
            #pragma unroll
            for (int i = 0; i < 8; i++) {
                int idx = tid + i * 128;
                int r = idx >> 4;
                int c4 = (idx & 15) << 2;
                cpa16(saddr(&Kb[r * KPAD + c4]),
                      &K[(size_t)(kv0 + r) * DIM + colBase + c4]);
                cpa16(saddr(&Vb[r * VPAD + c4]),
                      &V[(size_t)(kv0 + r) * DIM + colBase + c4]);
            }
            cpa_commit();
            cpa_wait<1>();
        } else {
            cpa_wait<0>();
        }
        __syncthreads();   // tile kt visible

        const float* Ks = smem + (kt & 1) * KVSZ;
        const float* Vs = Ks + 64 * KPAD;

        // ---- S = Q @ K^T : both 16-row halves share each K fragment ------
        float sA[8][4], sB[8][4];
        #pragma unroll
        for (int j = 0; j < 8; j++)
            #pragma unroll
            for (int v = 0; v < 4; v++) { sA[j][v] = 0.f; sB[j][v] = 0.f; }
        #pragma unroll
        for (int s = 0; s < 8; s++) {
            unsigned b0[8], b1[8];
            #pragma unroll
            for (int j = 0; j < 8; j++) {
                b0[j] = fu(Ks[(8 * j + g) * KPAD + 8 * s + q]);
                b1[j] = fu(Ks[(8 * j + g) * KPAD + 8 * s + q + 4]);
            }
            #pragma unroll
            for (int j = 0; j < 8; j++) {
                mma_tf32(sA[j], qa[s][0], qa[s][1], qa[s][2], qa[s][3], b0[j], b1[j]);
                mma_tf32(sB[j], qa[s][4], qa[s][5], qa[s][6], qa[s][7], b0[j], b1[j]);
            }
        }

        // ---- online softmax, exp2 domain (4 row-groups per lane) ---------
        float mxa0 = -INFINITY, mxa1 = -INFINITY, mxb0 = -INFINITY, mxb1 = -INFINITY;
        #pragma unroll
        for (int j = 0; j < 8; j++) {
            mxa0 = fmaxf(mxa0, fmaxf(sA[j][0], sA[j][1]));
            mxa1 = fmaxf(mxa1, fmaxf(sA[j][2], sA[j][3]));
            mxb0 = fmaxf(mxb0, fmaxf(sB[j][0], sB[j][1]));
            mxb1 = fmaxf(mxb1, fmaxf(sB[j][2], sB[j][3]));
        }
        #pragma unroll
        for (int msk = 1; msk < 4; msk <<= 1) {
            mxa0 = fmaxf(mxa0, __shfl_xor_sync(0xffffffffu, mxa0, msk));
            mxa1 = fmaxf(mxa1, __shfl_xor_sync(0xffffffffu, mxa1, msk));
            mxb0 = fmaxf(mxb0, __shfl_xor_sync(0xffffffffu, mxb0, msk));
            mxb1 = fmaxf(mxb1, __shfl_xor_sync(0xffffffffu, mxb1, msk));
        }
        float mn0 = fmaxf(m0, mxa0), mn1 = fmaxf(m1, mxa1);
        float mn2 = fmaxf(m2, mxb0), mn3 = fmaxf(m3, mxb1);
        float al0 = exp2f(m0 - mn0), al1 = exp2f(m1 - mn1);
        float al2 = exp2f(m2 - mn2), al3 = exp2f(m3 - mn3);
        m0 = mn0; m1 = mn1; m2 = mn2; m3 = mn3;

        float rs0 = 0.f, rs1 = 0.f, rs2 = 0.f, rs3 = 0.f;
        #pragma unroll
        for (int j = 0; j < 8; j++) {
            float p0 = exp2f(sA[j][0] - mn0);
            float p1 = exp2f(sA[j][1] - mn0);
            float p2 = exp2f(sA[j][2] - mn1);
            float p3 = exp2f(sA[j][3] - mn1);
            sA[j][0] = p0; sA[j][1] = p1; sA[j][2] = p2; sA[j][3] = p3;
            rs0 += p0 + p1; rs1 += p2 + p3;
            float r0v = exp2f(sB[j][0] - mn2);
            float r1v = exp2f(sB[j][1] - mn2);
            float r2v = exp2f(sB[j][2] - mn3);
            float r3v = exp2f(sB[j][3] - mn3);
            sB[j][0] = r0v; sB[j][1] = r1v; sB[j][2] = r2v; sB[j][3] = r3v;
            rs2 += r0v + r1v; rs3 += r2v + r3v;
        }
        #pragma unroll
        for (int msk = 1; msk < 4; msk <<= 1) {
            rs0 += __shfl_xor_sync(0xffffffffu, rs0, msk);
            rs1 += __shfl_xor_sync(0xffffffffu, rs1, msk);
            rs2 += __shfl_xor_sync(0xffffffffu, rs2, msk);
            rs3 += __shfl_xor_sync(0xffffffffu, rs3, msk);
        }
        l0 = l0 * al0 + rs0; l1 = l1 * al1 + rs1;
        l2 = l2 * al2 + rs2; l3 = l3 * al3 + rs3;
        #pragma unroll
        for (int j = 0; j < 8; j++) {
            oA[j][0] *= al0; oA[j][1] *= al0; oA[j][2] *= al1; oA[j][3] *= al1;
            oB[j][0] *= al2; oB[j][1] *= al2; oB[j][2] *= al3; oB[j][3] *= al3;
        }

        // ---- P -> per-warp smem slab (tf32) ------------------------------
        #pragma unroll
        for (int j = 0; j < 8; j++) {
            int col = 8 * j + 2 * q;
            *reinterpret_cast<float2*>(&Pw[g * PPAD + col]) =
                make_float2(tf32r(sA[j][0]), tf32r(sA[j][1]));
            *reinterpret_cast<float2*>(&Pw[(g + 8) * PPAD + col]) =
                make_float2(tf32r(sA[j][2]), tf32r(sA[j][3]));
            *reinterpret_cast<float2*>(&Pw[(g + 16) * PPAD + col]) =
                make_float2(tf32r(sB[j][0]), tf32r(sB[j][1]));
            *reinterpret_cast<float2*>(&Pw[(g + 24) * PPAD + col]) =
                make_float2(tf32r(sB[j][2]), tf32r(sB[j][3]));
        }
        __syncwarp();

        // ---- O += P @ V : V fragments shared by both halves --------------
        #pragma unroll
        for (int s = 0; s < 8; s++) {
            unsigned a0 = fu(Pw[g * PPAD + 8 * s + q]);
            unsigned a1 = fu(Pw[(g + 8) * PPAD + 8 * s + q]);
            unsigned a2 = fu(Pw[g * PPAD + 8 * s + q + 4]);
            unsigned a3 = fu(Pw[(g + 8) * PPAD + 8 * s + q + 4]);
            unsigned c0 = fu(Pw[(g + 16) * PPAD + 8 * s + q]);
            unsigned c1 = fu(Pw[(g + 24) * PPAD + 8 * s + q]);
            unsigned c2 = fu(Pw[(g + 16) * PPAD + 8 * s + q + 4]);
            unsigned c3 = fu(Pw[(g + 24) * PPAD + 8 * s + q + 4]);
            unsigned b0[8], b1[8];
            #pragma unroll
            for (int j = 0; j < 8; j++) {
                b0[j] = fu(Vs[(8 * s + q) * VPAD + 8 * j + g]);
                b1[j] = fu(Vs[(8 * s + q + 4) * VPAD + 8 * j + g]);
            }
            #pragma unroll
            for (int j = 0; j < 8; j++) {
                mma_tf32(oA[j], a0, a1, a2, a3, b0[j], b1[j]);
                mma_tf32(oB[j], c0, c1, c2, c3, b0[j], b1[j]);
            }
        }
    }

    // normalize + write, tf32-rounded (feeds cvt-free O-projection GEMM)
    float inv0 = 1.f / l0, inv1 = 1.f / l1, inv2 = 1.f / l2, inv3 = 1.f / l3;
    int r0 = q0 + warp * 32 + g;
    #pragma unroll
    for (int j = 0; j < 8; j++) {
        int col = colBase + 8 * j + 2 * q;
        *reinterpret_cast<float2*>(&AO[(size_t)r0 * DIM + col]) =
            make_float2(tf32r(oA[j][0] * inv0), tf32r(oA[j][1] * inv0));
        *reinterpret_cast<float2*>(&AO[(size_t)(r0 + 8) * DIM + col]) =
            make_float2(tf32r(oA[j][2] * inv1), tf32r(oA[j][3] * inv1));
        *reinterpret_cast<float2*>(&AO[(size_t)(r0 + 16) * DIM + col]) =
            make_float2(tf32r(oB[j][0] * inv2), tf32r(oB[j][1] * inv2));
        *reinterpret_cast<float2*>(&AO[(size_t)(r0 + 24) * DIM + col]) =
            make_float2(tf32r(oB[j][2] * inv3), tf32r(oB[j][3] * inv3));
    }
}

// ---------------- launch ---------------------------------------------------
extern "C" void kernel_launch(void* const* d_in, const int* in_sizes, int n_in,
                              void* d_out, int out_size) {
    const float* q   = (const float*)d_in[0];
    const float* kv  = (const float*)d_in[1];
    const float* q_w = (const float*)d_in[2];
    const float* q_b = (const float*)d_in[3];
    const float* k_w = (const float*)d_in[4];
    const float* k_b = (const float*)d_in[5];
    const float* v_w = (const float*)d_in[6];
    const float* v_b = (const float*)d_in[7];
    const float* o_w = (const float*)d_in[8];
    const float* o_b = (const float*)d_in[9];
    float* out = (float*)d_out;

    float *Q, *K, *V, *AO, *X, *KV, *Wq, *Wk, *Wv, *Wo;
    cudaGetSymbolAddress((void**)&Q,  g_Q);
    cudaGetSymbolAddress((void**)&K,  g_K);
    cudaGetSymbolAddress((void**)&V,  g_V);
    cudaGetSymbolAddress((void**)&AO, g_AO);
    cudaGetSymbolAddress((void**)&X,  g_X);
    cudaGetSymbolAddress((void**)&KV, g_KV);
    cudaGetSymbolAddress((void**)&Wq, g_Wq);
    cudaGetSymbolAddress((void**)&Wk, g_Wk);
    cudaGetSymbolAddress((void**)&Wv, g_Wv);
    cudaGetSymbolAddress((void**)&Wo, g_Wo);

    // pre-round inputs + weights to tf32 (cp.async GEMMs stage raw bytes)
    const int nTok4 = NQ * DIM / 4;     // 1,048,576
    const int nW4   = DIM * DIM / 4;    // 262,144
    round4_kernel<<<nTok4 / 256, 256>>>((const float4*)q,   (float4*)X,  nTok4);
    round4_kernel<<<nTok4 / 256, 256>>>((const float4*)kv,  (float4*)KV, nTok4);
    round4_kernel<<<nW4 / 256, 256>>>((const float4*)q_w, (float4*)Wq, nW4);
    round4_kernel<<<nW4 / 256, 256>>>((const float4*)k_w, (float4*)Wk, nW4);
    round4_kernel<<<nW4 / 256, 256>>>((const float4*)v_w, (float4*)Wv, nW4);
    round4_kernel<<<nW4 / 256, 256>>>((const float4*)o_w, (float4*)Wo, nW4);

    cudaFuncSetAttribute(gemm_tf32, cudaFuncAttributeMaxDynamicSharedMemorySize,
                         GEMM_SMEM);

    dim3 gGrid(NQ / BM, DIM / BN);  // 32 x 8
    gemm_tf32<<<gGrid, 256, GEMM_SMEM>>>(X,  Wq, q_b, Q, NQ,  DIM, DIM, 1);
    gemm_tf32<<<gGrid, 256, GEMM_SMEM>>>(KV, Wk, k_b, K, NKV, DIM, DIM, 1);
    gemm_tf32<<<gGrid, 256, GEMM_SMEM>>>(KV, Wv, v_b, V, NKV, DIM, DIM, 1);

    const size_t attnSmem = (size_t)(2 * KVSZ + 128 * PPAD) * sizeof(float); // 110592
    cudaFuncSetAttribute(attn_tf32, cudaFuncAttributeMaxDynamicSharedMemorySize,
                         (int)attnSmem);
    dim3 aGrid(NQ / 128, NH);       // 32 x 16
    attn_tf32<<<aGrid, 128, attnSmem>>>(Q, K, V, AO);

    gemm_tf32<<<gGrid, 256, GEMM_SMEM>>>(AO, Wo, o_b, out, NQ, DIM, DIM, 0);
}

// round 11
// speedup vs baseline: 1.7289x; 1.0476x over previous
#include <cuda_runtime.h>
#include <math.h>

#define DIM 1024
#define NQ 4096
#define NKV 4096
#define NH 16
#define HD 64

// ---------------- scratch (device globals; no allocation allowed) ----------
__device__ float g_Q[NQ * DIM];
__device__ float g_K[NKV * DIM];
__device__ float g_V[NKV * DIM];
__device__ float g_AO[NQ * DIM];
__device__ float g_X[NQ * DIM];     // tf32-rounded q input
__device__ float g_KV[NKV * DIM];   // tf32-rounded kv input
__device__ float g_Wq[DIM * DIM];
__device__ float g_Wk[DIM * DIM];
__device__ float g_Wv[DIM * DIM];
__device__ float g_Wo[DIM * DIM];

// ---------------- helpers ---------------------------------------------------
__device__ __forceinline__ float tf32r(float x) {
    unsigned u;
    asm("cvt.rna.tf32.f32 %0, %1;" : "=r"(u) : "f"(x));
    return __uint_as_float(u);
}
__device__ __forceinline__ unsigned fu(float x) { return __float_as_uint(x); }

__device__ __forceinline__ void mma_tf32(float c[4],
                                         unsigned a0, unsigned a1, unsigned a2, unsigned a3,
                                         unsigned b0, unsigned b1) {
    asm volatile(
        "mma.sync.aligned.m16n8k8.row.col.f32.tf32.tf32.f32 "
        "{%0,%1,%2,%3},{%4,%5,%6,%7},{%8,%9},{%0,%1,%2,%3};"
        : "+f"(c[0]), "+f"(c[1]), "+f"(c[2]), "+f"(c[3])
        : "r"(a0), "r"(a1), "r"(a2), "r"(a3), "r"(b0), "r"(b1));
}

__device__ __forceinline__ unsigned saddr(const void* p) {
    return (unsigned)__cvta_generic_to_shared(p);
}
__device__ __forceinline__ void cpa16(unsigned dst, const float* src) {
    asm volatile("cp.async.cg.shared.global [%0], [%1], 16;" :: "r"(dst), "l"(src));
}
__device__ __forceinline__ void cpa_commit() {
    asm volatile("cp.async.commit_group;");
}
template <int N> __device__ __forceinline__ void cpa_wait() {
    asm volatile("cp.async.wait_group %0;" :: "n"(N));
}

// ---------------- pre-round pass: dst = tf32r(src) -------------------------
__global__ __launch_bounds__(256)
void round4_kernel(const float4* __restrict__ src, float4* __restrict__ dst, int n4) {
    int i = blockIdx.x * blockDim.x + threadIdx.x;
    if (i < n4) {
        float4 v = src[i];
        dst[i] = make_float4(tf32r(v.x), tf32r(v.y), tf32r(v.z), tf32r(v.w));
    }
}

// ---------------- GEMM: C[M,N] = X[M,K] @ W[N,K]^T + b ---------------------
// inputs pre-rounded to tf32; cp.async double-buffered pipeline.
#define BM 128
#define BN 128
#define BK 32
#define GP 36   // smem row pad

#define GEMM_SMEM ((2 * BM * GP + 2 * BN * GP) * 4)

__global__ __launch_bounds__(256, 2)
void gemm_tf32(const float* __restrict__ X, const float* __restrict__ W,
               const float* __restrict__ bias, float* __restrict__ C,
               int M, int N, int K, int roundOut) {
    extern __shared__ float gs[];
    // layout: Xs[2][BM][GP], Ws[2][BN][GP]
    const int tid = threadIdx.x;
    const int warp = tid >> 5, lane = tid & 31;
    const int g = lane >> 2, q = lane & 3;
    const int wm = warp >> 1, wn = warp & 1;          // 4 x 2 warp grid
    const int rowBase = blockIdx.x * BM;
    const int colBase = blockIdx.y * BN;
    const int NT = K / BK;

    float acc[2][8][4];
    #pragma unroll
    for (int i = 0; i < 2; i++)
        #pragma unroll
        for (int j = 0; j < 8; j++)
            #pragma unroll
            for (int v = 0; v < 4; v++) acc[i][j][v] = 0.f;

    // prologue: stage tile 0 into buffer 0
    {
        #pragma unroll
        for (int i = 0; i < 4; i++) {
            int idx = tid + i * 256;          // 0..1023
            int r = idx >> 3;                 // 0..127
            int c4 = (idx & 7) << 2;          // 0,4,..28
            cpa16(saddr(&gs[0 * BM * GP + r * GP + c4]),
                  &X[(size_t)(rowBase + r) * K + c4]);
            cpa16(saddr(&gs[2 * BM * GP + 0 * BN * GP + r * GP + c4]),
                  &W[(size_t)(colBase + r) * K + c4]);
        }
        cpa_commit();
    }

    for (int kt = 0; kt < NT; kt++) {
        __syncthreads();   // prior readers of the buffer we are about to fill are done
        if (kt + 1 < NT) {
            int k0 = (kt + 1) * BK;
            int buf = (kt + 1) & 1;
            #pragma unroll
            for (int i = 0; i < 4; i++) {
                int idx = tid + i * 256;
                int r = idx >> 3;
                int c4 = (idx & 7) << 2;
                cpa16(saddr(&gs[buf * BM * GP + r * GP + c4]),
                      &X[(size_t)(rowBase + r) * K + k0 + c4]);
                cpa16(saddr(&gs[2 * BM * GP + buf * BN * GP + r * GP + c4]),
                      &W[(size_t)(colBase + r) * K + k0 + c4]);
            }
            cpa_commit();
            cpa_wait<1>();
        } else {
            cpa_wait<0>();
        }
        __syncthreads();   // tile kt visible

        const float* Xs = gs + (kt & 1) * BM * GP;
        const float* Ws = gs + 2 * BM * GP + (kt & 1) * BN * GP;

        #pragma unroll
        for (int ks = 0; ks < 4; ks++) {
            const int kk = ks * 8;
            unsigned b0[8], b1[8];
            #pragma unroll
            for (int j = 0; j < 8; j++) {
                b0[j] = fu(Ws[(wn * 64 + j * 8 + g) * GP + kk + q]);
                b1[j] = fu(Ws[(wn * 64 + j * 8 + g) * GP + kk + q + 4]);
            }
            #pragma unroll
            for (int i = 0; i < 2; i++) {
                int mr = wm * 32 + i * 16 + g;
                unsigned a0 = fu(Xs[mr * GP + kk + q]);
                unsigned a1 = fu(Xs[(mr + 8) * GP + kk + q]);
                unsigned a2 = fu(Xs[mr * GP + kk + q + 4]);
                unsigned a3 = fu(Xs[(mr + 8) * GP + kk + q + 4]);
                #pragma unroll
                for (int j = 0; j < 8; j++)
                    mma_tf32(acc[i][j], a0, a1, a2, a3, b0[j], b1[j]);
            }
        }
    }

    #pragma unroll
    for (int i = 0; i < 2; i++) {
        int r0 = rowBase + wm * 32 + i * 16 + g;
        #pragma unroll
        for (int j = 0; j < 8; j++) {
            int col = colBase + wn * 64 + j * 8 + 2 * q;
            float2 bb = *reinterpret_cast<const float2*>(&bias[col]);
            float2 v0 = make_float2(acc[i][j][0] + bb.x, acc[i][j][1] + bb.y);
            float2 v1 = make_float2(acc[i][j][2] + bb.x, acc[i][j][3] + bb.y);
            if (roundOut) {
                v0.x = tf32r(v0.x); v0.y = tf32r(v0.y);
                v1.x = tf32r(v1.x); v1.y = tf32r(v1.y);
            }
            *reinterpret_cast<float2*>(&C[(size_t)r0 * N + col]) = v0;
            *reinterpret_cast<float2*>(&C[(size_t)(r0 + 8) * N + col]) = v1;
        }
    }
}

// ---------------- Flash attention (tf32 mma, shift-free softmax) -----------
// grid (NQ/128, NH), 128 threads (4 warps). Warp w owns q rows 32w..32w+31.
// K/V double-buffered via cp.async. Softmax computed WITHOUT max-shift:
// scores in log2 domain are bounded (|s| << 127), so p = exp2(s) directly;
// l accumulates per-lane across all tiles and is reduced once at the end.
#define KPAD 68
#define VPAD 72
#define PPAD 76
#define KVSZ (64 * KPAD + 64 * VPAD)   // floats per K/V buffer

__global__ __launch_bounds__(128, 2)
void attn_tf32(const float* __restrict__ Q, const float* __restrict__ K,
               const float* __restrict__ V, float* __restrict__ AO) {
    extern __shared__ float smem[];
    float* Ps = smem + 2 * KVSZ;            // 128 x 76

    const int tid = threadIdx.x;
    const int warp = tid >> 5, lane = tid & 31;
    const int g = lane >> 2, q = lane & 3;
    const int h = blockIdx.y;
    const int q0 = blockIdx.x * 128;
    const int colBase = h * HD;
    const int NT = NKV / 64;

    // hoist Q fragments straight from global; fold SCALE*log2(e)
    const float qsc = 0.125f * 1.44269504088896f;
    unsigned qa[8][8];   // [s][0..3]=rows g,g+8 | [4..7]=rows g+16,g+24
    {
        const float* Qr0 = Q + (size_t)(q0 + warp * 32 + g) * DIM + colBase;
        const float* Qr1 = Qr0 + (size_t)8 * DIM;
        const float* Qr2 = Qr0 + (size_t)16 * DIM;
        const float* Qr3 = Qr0 + (size_t)24 * DIM;
        #pragma unroll
        for (int s = 0; s < 8; s++) {
            qa[s][0] = fu(tf32r(Qr0[8 * s + q] * qsc));
            qa[s][1] = fu(tf32r(Qr1[8 * s + q] * qsc));
            qa[s][2] = fu(tf32r(Qr0[8 * s + q + 4] * qsc));
            qa[s][3] = fu(tf32r(Qr1[8 * s + q + 4] * qsc));
            qa[s][4] = fu(tf32r(Qr2[8 * s + q] * qsc));
            qa[s][5] = fu(tf32r(Qr3[8 * s + q] * qsc));
            qa[s][6] = fu(tf32r(Qr2[8 * s + q + 4] * qsc));
            qa[s][7] = fu(tf32r(Qr3[8 * s + q + 4] * qsc));
        }
    }

    float oA[8][4], oB[8][4];
    #pragma unroll
    for (int j = 0; j < 8; j++)
        #pragma unroll
        for (int v = 0; v < 4; v++) { oA[j][v] = 0.f; oB[j][v] = 0.f; }
    float l0 = 0.f, l1 = 0.f, l2 = 0.f, l3 = 0.f;   // per-lane partial sums

    float* Pw = Ps + warp * 32 * PPAD;      // per-warp-private 32-row P slab

    // prologue: stage tile 0 into buffer 0
    {
        #pragma unroll
        for (int i = 0; i < 8; i++) {
            int idx = tid + i * 128;        // 0..1023
            int r = idx >> 4;               // 0..63
            int c4 = (idx & 15) << 2;
            cpa16(saddr(&smem[r * KPAD + c4]),
                  &K[(size_t)r * DIM + colBase + c4]);
            cpa16(saddr(&smem[64 * KPAD + r * VPAD + c4]),
                  &V[(size_t)r * DIM + colBase + c4]);
        }
        cpa_commit();
    }

    for (int kt = 0; kt < NT; kt++) {
        __syncthreads();   // prior readers of buffer (kt+1)&1 done
        if (kt + 1 < NT) {
            int kv0 = (kt + 1) * 64;
            float* Kb = smem + ((kt + 1) & 1) * KVSZ;
            float* Vb = Kb + 64 * KPAD;
            #pragma unroll
            for (int i = 0; i < 8; i++) {
                int idx = tid + i * 128;
                int r = idx >> 4;
                int c4 = (idx & 15) << 2;
                cpa16(saddr(&Kb[r * KPAD + c4]),
                      &K[(size_t)(kv0 + r) * DIM + colBase + c4]);
                cpa16(saddr(&Vb[r * VPAD + c4]),
                      &V[(size_t)(kv0 + r) * DIM + colBase + c4]);
            }
            cpa_commit();
            cpa_wait<1>();
        } else {
            cpa_wait<0>();
        }
        __syncthreads();   // tile kt visible

        const float* Ks = smem + (kt & 1) * KVSZ;
        const float* Vs = Ks + 64 * KPAD;

        // ---- S = Q @ K^T : both 16-row halves share each K fragment ------
        float sA[8][4], sB[8][4];
        #pragma unroll
        for (int j = 0; j < 8; j++)
            #pragma unroll
            for (int v = 0; v < 4; v++) { sA[j][v] = 0.f; sB[j][v] = 0.f; }
        #pragma unroll
        for (int s = 0; s < 8; s++) {
            unsigned b0[8], b1[8];
            #pragma unroll
            for (int j = 0; j < 8; j++) {
                b0[j] = fu(Ks[(8 * j + g) * KPAD + 8 * s + q]);
                b1[j] = fu(Ks[(8 * j + g) * KPAD + 8 * s + q + 4]);
            }
            #pragma unroll
            for (int j = 0; j < 8; j++) {
                mma_tf32(sA[j], qa[s][0], qa[s][1], qa[s][2], qa[s][3], b0[j], b1[j]);
                mma_tf32(sB[j], qa[s][4], qa[s][5], qa[s][6], qa[s][7], b0[j], b1[j]);
            }
        }

        // ---- shift-free softmax: p = exp2(s), accumulate l per-lane ------
        #pragma unroll
        for (int j = 0; j < 8; j++) {
            float p0 = exp2f(sA[j][0]);
            float p1 = exp2f(sA[j][1]);
            float p2 = exp2f(sA[j][2]);
            float p3 = exp2f(sA[j][3]);
            sA[j][0] = p0; sA[j][1] = p1; sA[j][2] = p2; sA[j][3] = p3;
            l0 += p0 + p1; l1 += p2 + p3;
            float r0v = exp2f(sB[j][0]);
            float r1v = exp2f(sB[j][1]);
            float r2v = exp2f(sB[j][2]);
            float r3v = exp2f(sB[j][3]);
            sB[j][0] = r0v; sB[j][1] = r1v; sB[j][2] = r2v; sB[j][3] = r3v;
            l2 += r0v + r1v; l3 += r2v + r3v;
        }

        // ---- P -> per-warp smem slab (tf32) ------------------------------
        #pragma unroll
        for (int j = 0; j < 8; j++) {
            int col = 8 * j + 2 * q;
            *reinterpret_cast<float2*>(&Pw[g * PPAD + col]) =
                make_float2(tf32r(sA[j][0]), tf32r(sA[j][1]));
            *reinterpret_cast<float2*>(&Pw[(g + 8) * PPAD + col]) =
                make_float2(tf32r(sA[j][2]), tf32r(sA[j][3]));
            *reinterpret_cast<float2*>(&Pw[(g + 16) * PPAD + col]) =
                make_float2(tf32r(sB[j][0]), tf32r(sB[j][1]));
            *reinterpret_cast<float2*>(&Pw[(g + 24) * PPAD + col]) =
                make_float2(tf32r(sB[j][2]), tf32r(sB[j][3]));
        }
        __syncwarp();

        // ---- O += P @ V : V fragments shared by both halves --------------
        #pragma unroll
        for (int s = 0; s < 8; s++) {
            unsigned a0 = fu(Pw[g * PPAD + 8 * s + q]);
            unsigned a1 = fu(Pw[(g + 8) * PPAD + 8 * s + q]);
            unsigned a2 = fu(Pw[g * PPAD + 8 * s + q + 4]);
            unsigned a3 = fu(Pw[(g + 8) * PPAD + 8 * s + q + 4]);
            unsigned c0 = fu(Pw[(g + 16) * PPAD + 8 * s + q]);
            unsigned c1 = fu(Pw[(g + 24) * PPAD + 8 * s + q]);
            unsigned c2 = fu(Pw[(g + 16) * PPAD + 8 * s + q + 4]);
            unsigned c3 = fu(Pw[(g + 24) * PPAD + 8 * s + q + 4]);
            unsigned b0[8], b1[8];
            #pragma unroll
            for (int j = 0; j < 8; j++) {
                b0[j] = fu(Vs[(8 * s + q) * VPAD + 8 * j + g]);
                b1[j] = fu(Vs[(8 * s + q + 4) * VPAD + 8 * j + g]);
            }
            #pragma unroll
            for (int j = 0; j < 8; j++) {
                mma_tf32(oA[j], a0, a1, a2, a3, b0[j], b1[j]);
                mma_tf32(oB[j], c0, c1, c2, c3, b0[j], b1[j]);
            }
        }
    }

    // final l reduction (once), normalize + write (tf32-rounded for O GEMM)
    #pragma unroll
    for (int msk = 1; msk < 4; msk <<= 1) {
        l0 += __shfl_xor_sync(0xffffffffu, l0, msk);
        l1 += __shfl_xor_sync(0xffffffffu, l1, msk);
        l2 += __shfl_xor_sync(0xffffffffu, l2, msk);
        l3 += __shfl_xor_sync(0xffffffffu, l3, msk);
    }
    float inv0 = 1.f / l0, inv1 = 1.f / l1, inv2 = 1.f / l2, inv3 = 1.f / l3;
    int r0 = q0 + warp * 32 + g;
    #pragma unroll
    for (int j = 0; j < 8; j++) {
        int col = colBase + 8 * j + 2 * q;
        *reinterpret_cast<float2*>(&AO[(size_t)r0 * DIM + col]) =
            make_float2(tf32r(oA[j][0] * inv0), tf32r(oA[j][1] * inv0));
        *reinterpret_cast<float2*>(&AO[(size_t)(r0 + 8) * DIM + col]) =
            make_float2(tf32r(oA[j][2] * inv1), tf32r(oA[j][3] * inv1));
        *reinterpret_cast<float2*>(&AO[(size_t)(r0 + 16) * DIM + col]) =
            make_float2(tf32r(oB[j][0] * inv2), tf32r(oB[j][1] * inv2));
        *reinterpret_cast<float2*>(&AO[(size_t)(r0 + 24) * DIM + col]) =
            make_float2(tf32r(oB[j][2] * inv3), tf32r(oB[j][3] * inv3));
    }
}

// ---------------- launch ---------------------------------------------------
extern "C" void kernel_launch(void* const* d_in, const int* in_sizes, int n_in,
                              void* d_out, int out_size) {
    const float* q   = (const float*)d_in[0];
    const float* kv  = (const float*)d_in[1];
    const float* q_w = (const float*)d_in[2];
    const float* q_b = (const float*)d_in[3];
    const float* k_w = (const float*)d_in[4];
    const float* k_b = (const float*)d_in[5];
    const float* v_w = (const float*)d_in[6];
    const float* v_b = (const float*)d_in[7];
    const float* o_w = (const float*)d_in[8];
    const float* o_b = (const float*)d_in[9];
    float* out = (float*)d_out;

    float *Q, *K, *V, *AO, *X, *KV, *Wq, *Wk, *Wv, *Wo;
    cudaGetSymbolAddress((void**)&Q,  g_Q);
    cudaGetSymbolAddress((void**)&K,  g_K);
    cudaGetSymbolAddress((void**)&V,  g_V);
    cudaGetSymbolAddress((void**)&AO, g_AO);
    cudaGetSymbolAddress((void**)&X,  g_X);
    cudaGetSymbolAddress((void**)&KV, g_KV);
    cudaGetSymbolAddress((void**)&Wq, g_Wq);
    cudaGetSymbolAddress((void**)&Wk, g_Wk);
    cudaGetSymbolAddress((void**)&Wv, g_Wv);
    cudaGetSymbolAddress((void**)&Wo, g_Wo);

    // pre-round inputs + weights to tf32 (cp.async GEMMs stage raw bytes)
    const int nTok4 = NQ * DIM / 4;     // 1,048,576
    const int nW4   = DIM * DIM / 4;    // 262,144
    round4_kernel<<<nTok4 / 256, 256>>>((const float4*)q,   (float4*)X,  nTok4);
    round4_kernel<<<nTok4 / 256, 256>>>((const float4*)kv,  (float4*)KV, nTok4);
    round4_kernel<<<nW4 / 256, 256>>>((const float4*)q_w, (float4*)Wq, nW4);
    round4_kernel<<<nW4 / 256, 256>>>((const float4*)k_w, (float4*)Wk, nW4);
    round4_kernel<<<nW4 / 256, 256>>>((const float4*)v_w, (float4*)Wv, nW4);
    round4_kernel<<<nW4 / 256, 256>>>((const float4*)o_w, (float4*)Wo, nW4);

    cudaFuncSetAttribute(gemm_tf32, cudaFuncAttributeMaxDynamicSharedMemorySize,
                         GEMM_SMEM);

    dim3 gGrid(NQ / BM, DIM / BN);  // 32 x 8
    gemm_tf32<<<gGrid, 256, GEMM_SMEM>>>(X,  Wq, q_b, Q, NQ,  DIM, DIM, 0);
    gemm_tf32<<<gGrid, 256, GEMM_SMEM>>>(KV, Wk, k_b, K, NKV, DIM, DIM, 1);
    gemm_tf32<<<gGrid, 256, GEMM_SMEM>>>(KV, Wv, v_b, V, NKV, DIM, DIM, 1);

    const size_t attnSmem = (size_t)(2 * KVSZ + 128 * PPAD) * sizeof(float); // 110592
    cudaFuncSetAttribute(attn_tf32, cudaFuncAttributeMaxDynamicSharedMemorySize,
                         (int)attnSmem);
    dim3 aGrid(NQ / 128, NH);       // 32 x 16
    attn_tf32<<<aGrid, 128, attnSmem>>>(Q, K, V, AO);

    gemm_tf32<<<gGrid, 256, GEMM_SMEM>>>(AO, Wo, o_b, out, NQ, DIM, DIM, 0);
}

// round 13
// speedup vs baseline: 3.0320x; 1.7537x over previous
#include <cuda_runtime.h>
#include <cuda_fp16.h>
#include <math.h>

#define DIM 1024
#define NQ 4096
#define NKV 4096
#define NH 16
#define HD 64

// ---------------- scratch (device globals; no allocation allowed) ----------
__device__ __half g_Xh[NQ * DIM];
__device__ __half g_KVh[NKV * DIM];
__device__ __half g_Wqh[DIM * DIM];
__device__ __half g_Wkh[DIM * DIM];
__device__ __half g_Wvh[DIM * DIM];
__device__ __half g_Woh[DIM * DIM];
__device__ __half g_Qh[NQ * DIM];
__device__ __half g_Kh[NKV * DIM];
__device__ __half g_Vh[NKV * DIM];
__device__ __half g_AOh[NQ * DIM];

// ---------------- helpers ---------------------------------------------------
__device__ __forceinline__ unsigned saddr(const void* p) {
    return (unsigned)__cvta_generic_to_shared(p);
}
__device__ __forceinline__ void cpa16(unsigned dst, const void* src) {
    asm volatile("cp.async.cg.shared.global [%0], [%1], 16;" :: "r"(dst), "l"(src));
}
__device__ __forceinline__ void cpa_commit() {
    asm volatile("cp.async.commit_group;");
}
template <int N> __device__ __forceinline__ void cpa_wait() {
    asm volatile("cp.async.wait_group %0;" :: "n"(N));
}

__device__ __forceinline__ void mma_f16(float c[4],
                                        unsigned a0, unsigned a1, unsigned a2, unsigned a3,
                                        unsigned b0, unsigned b1) {
    asm volatile(
        "mma.sync.aligned.m16n8k16.row.col.f32.f16.f16.f32 "
        "{%0,%1,%2,%3},{%4,%5,%6,%7},{%8,%9},{%0,%1,%2,%3};"
        : "+f"(c[0]), "+f"(c[1]), "+f"(c[2]), "+f"(c[3])
        : "r"(a0), "r"(a1), "r"(a2), "r"(a3), "r"(b0), "r"(b1));
}

__device__ __forceinline__ void ldsm4t(unsigned& r0, unsigned& r1,
                                       unsigned& r2, unsigned& r3, unsigned addr) {
    asm volatile("ldmatrix.sync.aligned.m8n8.x4.trans.shared.b16 {%0,%1,%2,%3}, [%4];"
                 : "=r"(r0), "=r"(r1), "=r"(r2), "=r"(r3) : "r"(addr));
}

__device__ __forceinline__ unsigned lduh(const __half* p) {
    return *reinterpret_cast<const unsigned*>(p);
}
__device__ __forceinline__ unsigned ldsh(const __half* p) {
    return *reinterpret_cast<const unsigned*>(p);
}

// ---------------- pre-pass: float -> half ----------------------------------
__global__ __launch_bounds__(256)
void f2h_kernel(const float4* __restrict__ src, uint2* __restrict__ dst, int n4) {
    int i = blockIdx.x * blockDim.x + threadIdx.x;
    if (i < n4) {
        float4 v = src[i];
        uint2 o;
        o.x = __half2_raw(__floats2half2_rn(v.x, v.y)).x |
              ((unsigned)__half2_raw(__floats2half2_rn(v.x, v.y)).y << 16);
        // simpler: pack via intrinsics
        __half2 h0 = __floats2half2_rn(v.x, v.y);
        __half2 h1 = __floats2half2_rn(v.z, v.w);
        o.x = *reinterpret_cast<unsigned*>(&h0);
        o.y = *reinterpret_cast<unsigned*>(&h1);
        dst[i] = o;
    }
}

// ---------------- GEMM (fp16 mma): C[M,N] = X @ W^T + b --------------------
// 128x128x32 tiles, 256 threads (8 warps 4x2), warp tile 32x64, k-step 16.
#define BM 128
#define BN 128
#define BK 32
#define GPH 40   // smem row width in halves (80B, stride 20 words)

#define GEMM_SMEM ((2 * BM * GPH + 2 * BN * GPH) * 2)

__global__ __launch_bounds__(256, 2)
void gemm_f16(const __half* __restrict__ X, const __half* __restrict__ W,
              const float* __restrict__ bias, void* __restrict__ Cout,
              int M, int N, int K, float outScale, int outHalf) {
    extern __shared__ __half gsh[];
    __half* Xs0 = gsh;                               // [2][BM][GPH]
    __half* Ws0 = gsh + 2 * BM * GPH;                // [2][BN][GPH]

    const int tid = threadIdx.x;
    const int warp = tid >> 5, lane = tid & 31;
    const int g = lane >> 2, q = lane & 3;
    const int wm = warp >> 1, wn = warp & 1;
    const int rowBase = blockIdx.x * BM;
    const int colBase = blockIdx.y * BN;
    const int NT = K / BK;

    float acc[2][8][4];
    #pragma unroll
    for (int i = 0; i < 2; i++)
        #pragma unroll
        for (int j = 0; j < 8; j++)
            #pragma unroll
            for (int v = 0; v < 4; v++) acc[i][j][v] = 0.f;

    // prologue: tile 0 -> buffer 0  (512 chunks X + 512 W, 8 halves each)
    {
        #pragma unroll
        for (int i = 0; i < 2; i++) {
            int idx = tid + i * 256;          // 0..511
            int r = idx >> 2, c = idx & 3;    // r 0..127, c 0..3
            cpa16(saddr(&Xs0[r * GPH + c * 8]), &X[(size_t)(rowBase + r) * K + c * 8]);
            cpa16(saddr(&Ws0[r * GPH + c * 8]), &W[(size_t)(colBase + r) * K + c * 8]);
        }
        cpa_commit();
    }

    for (int kt = 0; kt < NT; kt++) {
        __syncthreads();
        if (kt + 1 < NT) {
            int k0 = (kt + 1) * BK;
            int buf = (kt + 1) & 1;
            __half* Xb = Xs0 + buf * BM * GPH;
            __half* Wb = Ws0 + buf * BN * GPH;
            #pragma unroll
            for (int i = 0; i < 2; i++) {
                int idx = tid + i * 256;
                int r = idx >> 2, c = idx & 3;
                cpa16(saddr(&Xb[r * GPH + c * 8]), &X[(size_t)(rowBase + r) * K + k0 + c * 8]);
                cpa16(saddr(&Wb[r * GPH + c * 8]), &W[(size_t)(colBase + r) * K + k0 + c * 8]);
            }
            cpa_commit();
            cpa_wait<1>();
        } else {
            cpa_wait<0>();
        }
        __syncthreads();

        const __half* Xs = Xs0 + (kt & 1) * BM * GPH;
        const __half* Ws = Ws0 + (kt & 1) * BN * GPH;

        #pragma unroll
        for (int ks = 0; ks < 2; ks++) {          // two k16 steps per BK=32
            const int kh = ks * 16;
            unsigned b0[8], b1[8];
            #pragma unroll
            for (int j = 0; j < 8; j++) {
                const __half* wr = &Ws[(wn * 64 + j * 8 + g) * GPH + kh];
                b0[j] = ldsh(&wr[2 * q]);
                b1[j] = ldsh(&wr[2 * q + 8]);
            }
            #pragma unroll
            for (int i = 0; i < 2; i++) {
                int mr = wm * 32 + i * 16 + g;
                unsigned a0 = ldsh(&Xs[mr * GPH + kh + 2 * q]);
                unsigned a1 = ldsh(&Xs[(mr + 8) * GPH + kh + 2 * q]);
                unsigned a2 = ldsh(&Xs[mr * GPH + kh + 2 * q + 8]);
                unsigned a3 = ldsh(&Xs[(mr + 8) * GPH + kh + 2 * q + 8]);
                #pragma unroll
                for (int j = 0; j < 8; j++)
                    mma_f16(acc[i][j], a0, a1, a2, a3, b0[j], b1[j]);
            }
        }
    }

    // epilogue
    #pragma unroll
    for (int i = 0; i < 2; i++) {
        int r0 = rowBase + wm * 32 + i * 16 + g;
        #pragma unroll
        for (int j = 0; j < 8; j++) {
            int col = colBase + wn * 64 + j * 8 + 2 * q;
            float2 bb = *reinterpret_cast<const float2*>(&bias[col]);
            float c00 = (acc[i][j][0] + bb.x) * outScale;
            float c01 = (acc[i][j][1] + bb.y) * outScale;
            float c10 = (acc[i][j][2] + bb.x) * outScale;
            float c11 = (acc[i][j][3] + bb.y) * outScale;
            if (outHalf) {
                __half* Ch = (__half*)Cout;
                __half2 h0 = __floats2half2_rn(c00, c01);
                __half2 h1 = __floats2half2_rn(c10, c11);
                *reinterpret_cast<__half2*>(&Ch[(size_t)r0 * N + col]) = h0;
                *reinterpret_cast<__half2*>(&Ch[(size_t)(r0 + 8) * N + col]) = h1;
            } else {
                float* Cf = (float*)Cout;
                *reinterpret_cast<float2*>(&Cf[(size_t)r0 * N + col]) = make_float2(c00, c01);
                *reinterpret_cast<float2*>(&Cf[(size_t)(r0 + 8) * N + col]) = make_float2(c10, c11);
            }
        }
    }
}

// ---------------- Flash attention (fp16 mma, shift-free softmax) -----------
// grid (NQ/128, NH), 128 threads (4 warps). Warp w owns q rows 32w..32w+31.
// K/V fp16, double-buffered cp.async. V B-frags via ldmatrix.x4.trans.
#define KPH 72   // K/V smem row width in halves (144B, stride 36 words)
#define PPH 72   // P slab row width in halves
#define KVSZH (64 * KPH + 64 * KPH)   // halves per K+V buffer

__global__ __launch_bounds__(128, 2)
void attn_f16(const __half* __restrict__ Q, const __half* __restrict__ K,
              const __half* __restrict__ V, __half* __restrict__ AO) {
    extern __shared__ __half smh[];
    __half* Ps = smh + 2 * KVSZH;          // 128 x 72 halves

    const int tid = threadIdx.x;
    const int warp = tid >> 5, lane = tid & 31;
    const int g = lane >> 2, q = lane & 3;
    const int h = blockIdx.y;
    const int q0 = blockIdx.x * 128;
    const int colBase = h * HD;
    const int NT = NKV / 64;

    // hoist Q fragments (scale pre-folded at Q-projection epilogue)
    unsigned qa[4][4], qc[4][4];   // [k16 step][a0..a3]: rows {g,g+8}, {g+16,g+24}
    {
        const __half* Qr0 = Q + (size_t)(q0 + warp * 32 + g) * DIM + colBase;
        const __half* Qr1 = Qr0 + (size_t)8 * DIM;
        const __half* Qr2 = Qr0 + (size_t)16 * DIM;
        const __half* Qr3 = Qr0 + (size_t)24 * DIM;
        #pragma unroll
        for (int s = 0; s < 4; s++) {
            qa[s][0] = lduh(&Qr0[16 * s + 2 * q]);
            qa[s][1] = lduh(&Qr1[16 * s + 2 * q]);
            qa[s][2] = lduh(&Qr0[16 * s + 2 * q + 8]);
            qa[s][3] = lduh(&Qr1[16 * s + 2 * q + 8]);
            qc[s][0] = lduh(&Qr2[16 * s + 2 * q]);
            qc[s][1] = lduh(&Qr3[16 * s + 2 * q]);
            qc[s][2] = lduh(&Qr2[16 * s + 2 * q + 8]);
            qc[s][3] = lduh(&Qr3[16 * s + 2 * q + 8]);
        }
    }

    float oA[8][4], oB[8][4];
    #pragma unroll
    for (int j = 0; j < 8; j++)
        #pragma unroll
        for (int v = 0; v < 4; v++) { oA[j][v] = 0.f; oB[j][v] = 0.f; }
    float l0 = 0.f, l1 = 0.f, l2 = 0.f, l3 = 0.f;

    __half* Pw = Ps + warp * 32 * PPH;

    // V ldmatrix lane address components
    const int lm = lane >> 3, lr = lane & 7;      // matrix id, row within matrix

    // prologue: stage tile 0 into buffer 0 (512 chunks K + 512 V, 8 halves)
    {
        #pragma unroll
        for (int i = 0; i < 4; i++) {
            int idx = tid + i * 128;        // 0..511
            int r = idx >> 3, c = idx & 7;
            cpa16(saddr(&smh[r * KPH + c * 8]), &K[(size_t)r * DIM + colBase + c * 8]);
            cpa16(saddr(&smh[64 * KPH + r * KPH + c * 8]), &V[(size_t)r * DIM + colBase + c * 8]);
        }
        cpa_commit();
    }

    for (int kt = 0; kt < NT; kt++) {
        __syncthreads();
        if (kt + 1 < NT) {
            int kv0 = (kt + 1) * 64;
            __half* Kb = smh + ((kt + 1) & 1) * KVSZH;
            __half* Vb = Kb + 64 * KPH;
            #pragma unroll
            for (int i = 0; i < 4; i++) {
                int idx = tid + i * 128;
                int r = idx >> 3, c = idx & 7;
                cpa16(saddr(&Kb[r * KPH + c * 8]), &K[(size_t)(kv0 + r) * DIM + colBase + c * 8]);
                cpa16(saddr(&Vb[r * KPH + c * 8]), &V[(size_t)(kv0 + r) * DIM + colBase + c * 8]);
            }
            cpa_commit();
            cpa_wait<1>();
        } else {
            cpa_wait<0>();
        }
        __syncthreads();

        const __half* Ks = smh + (kt & 1) * KVSZH;
        const __half* Vs = Ks + 64 * KPH;

        // ---- S = Q @ K^T --------------------------------------------------
        float sA[8][4], sB[8][4];
        #pragma unroll
        for (int j = 0; j < 8; j++)
            #pragma unroll
            for (int v = 0; v < 4; v++) { sA[j][v] = 0.f; sB[j][v] = 0.f; }
        #pragma unroll
        for (int s = 0; s < 4; s++) {
            unsigned b0[8], b1[8];
            #pragma unroll
            for (int j = 0; j < 8; j++) {
                const __half* kr = &Ks[(8 * j + g) * KPH + 16 * s];
                b0[j] = ldsh(&kr[2 * q]);
                b1[j] = ldsh(&kr[2 * q + 8]);
            }
            #pragma unroll
            for (int j = 0; j < 8; j++) {
                mma_f16(sA[j], qa[s][0], qa[s][1], qa[s][2], qa[s][3], b0[j], b1[j]);
                mma_f16(sB[j], qc[s][0], qc[s][1], qc[s][2], qc[s][3], b0[j], b1[j]);
            }
        }

        // ---- shift-free softmax: p = exp2(s) ------------------------------
        #pragma unroll
        for (int j = 0; j < 8; j++) {
            float p0 = exp2f(sA[j][0]);
            float p1 = exp2f(sA[j][1]);
            float p2 = exp2f(sA[j][2]);
            float p3 = exp2f(sA[j][3]);
            sA[j][0] = p0; sA[j][1] = p1; sA[j][2] = p2; sA[j][3] = p3;
            l0 += p0 + p1; l1 += p2 + p3;
            float r0v = exp2f(sB[j][0]);
            float r1v = exp2f(sB[j][1]);
            float r2v = exp2f(sB[j][2]);
            float r3v = exp2f(sB[j][3]);
            sB[j][0] = r0v; sB[j][1] = r1v; sB[j][2] = r2v; sB[j][3] = r3v;
            l2 += r0v + r1v; l3 += r2v + r3v;
        }

        // ---- P -> per-warp smem slab (half2) ------------------------------
        #pragma unroll
        for (int j = 0; j < 8; j++) {
            int col = 8 * j + 2 * q;
            *reinterpret_cast<__half2*>(&Pw[g * PPH + col]) =
                __floats2half2_rn(sA[j][0], sA[j][1]);
            *reinterpret_cast<__half2*>(&Pw[(g + 8) * PPH + col]) =
                __floats2half2_rn(sA[j][2], sA[j][3]);
            *reinterpret_cast<__half2*>(&Pw[(g + 16) * PPH + col]) =
                __floats2half2_rn(sB[j][0], sB[j][1]);
            *reinterpret_cast<__half2*>(&Pw[(g + 24) * PPH + col]) =
                __floats2half2_rn(sB[j][2], sB[j][3]);
        }
        __syncwarp();

        // ---- O += P @ V (V B-frags via ldmatrix.x4.trans) -----------------
        #pragma unroll
        for (int s = 0; s < 4; s++) {      // k16 step over kv
            unsigned a0 = ldsh(&Pw[g * PPH + 16 * s + 2 * q]);
            unsigned a1 = ldsh(&Pw[(g + 8) * PPH + 16 * s + 2 * q]);
            unsigned a2 = ldsh(&Pw[g * PPH + 16 * s + 2 * q + 8]);
            unsigned a3 = ldsh(&Pw[(g + 8) * PPH + 16 * s + 2 * q + 8]);
            unsigned c0 = ldsh(&Pw[(g + 16) * PPH + 16 * s + 2 * q]);
            unsigned c1 = ldsh(&Pw[(g + 24) * PPH + 16 * s + 2 * q]);
            unsigned c2 = ldsh(&Pw[(g + 16) * PPH + 16 * s + 2 * q + 8]);
            unsigned c3 = ldsh(&Pw[(g + 24) * PPH + 16 * s + 2 * q + 8]);
            #pragma unroll
            for (int jj = 0; jj < 4; jj++) {   // covers j = 2jj, 2jj+1
                int kvrow = 16 * s + 8 * (lm & 1) + lr;
                int ncol = 16 * jj + 8 * (lm >> 1);
                unsigned vb0, vb1, vb2, vb3;
                ldsm4t(vb0, vb1, vb2, vb3, saddr(&Vs[kvrow * KPH + ncol]));
                mma_f16(oA[2 * jj + 0], a0, a1, a2, a3, vb0, vb1);
                mma_f16(oA[2 * jj + 1], a0, a1, a2, a3, vb2, vb3);
                mma_f16(oB[2 * jj + 0], c0, c1, c2, c3, vb0, vb1);
                mma_f16(oB[2 * jj + 1], c0, c1, c2, c3, vb2, vb3);
            }
        }
    }

    // final l reduction, normalize + write (half2, feeds O-proj GEMM)
    #pragma unroll
    for (int msk = 1; msk < 4; msk <<= 1) {
        l0 += __shfl_xor_sync(0xffffffffu, l0, msk);
        l1 += __shfl_xor_sync(0xffffffffu, l1, msk);
        l2 += __shfl_xor_sync(0xffffffffu, l2, msk);
        l3 += __shfl_xor_sync(0xffffffffu, l3, msk);
    }
    float inv0 = 1.f / l0, inv1 = 1.f / l1, inv2 = 1.f / l2, inv3 = 1.f / l3;
    int r0 = q0 + warp * 32 + g;
    #pragma unroll
    for (int j = 0; j < 8; j++) {
        int col = colBase + 8 * j + 2 * q;
        *reinterpret_cast<__half2*>(&AO[(size_t)r0 * DIM + col]) =
            __floats2half2_rn(oA[j][0] * inv0, oA[j][1] * inv0);
        *reinterpret_cast<__half2*>(&AO[(size_t)(r0 + 8) * DIM + col]) =
            __floats2half2_rn(oA[j][2] * inv1, oA[j][3] * inv1);
        *reinterpret_cast<__half2*>(&AO[(size_t)(r0 + 16) * DIM + col]) =
            __floats2half2_rn(oB[j][0] * inv2, oB[j][1] * inv2);
        *reinterpret_cast<__half2*>(&AO[(size_t)(r0 + 24) * DIM + col]) =
            __floats2half2_rn(oB[j][2] * inv3, oB[j][3] * inv3);
    }
}

// ---------------- launch ---------------------------------------------------
extern "C" void kernel_launch(void* const* d_in, const int* in_sizes, int n_in,
                              void* d_out, int out_size) {
    const float* q   = (const float*)d_in[0];
    const float* kv  = (const float*)d_in[1];
    const float* q_w = (const float*)d_in[2];
    const float* q_b = (const float*)d_in[3];
    const float* k_w = (const float*)d_in[4];
    const float* k_b = (const float*)d_in[5];
    const float* v_w = (const float*)d_in[6];
    const float* v_b = (const float*)d_in[7];
    const float* o_w = (const float*)d_in[8];
    const float* o_b = (const float*)d_in[9];
    float* out = (float*)d_out;

    __half *Xh, *KVh, *Wqh, *Wkh, *Wvh, *Woh, *Qh, *Kh, *Vh, *AOh;
    cudaGetSymbolAddress((void**)&Xh,  g_Xh);
    cudaGetSymbolAddress((void**)&KVh, g_KVh);
    cudaGetSymbolAddress((void**)&Wqh, g_Wqh);
    cudaGetSymbolAddress((void**)&Wkh, g_Wkh);
    cudaGetSymbolAddress((void**)&Wvh, g_Wvh);
    cudaGetSymbolAddress((void**)&Woh, g_Woh);
    cudaGetSymbolAddress((void**)&Qh,  g_Qh);
    cudaGetSymbolAddress((void**)&Kh,  g_Kh);
    cudaGetSymbolAddress((void**)&Vh,  g_Vh);
    cudaGetSymbolAddress((void**)&AOh, g_AOh);

    // pre-convert inputs + weights to fp16
    const int nTok4 = NQ * DIM / 4;
    const int nW4   = DIM * DIM / 4;
    f2h_kernel<<<nTok4 / 256, 256>>>((const float4*)q,   (uint2*)Xh,  nTok4);
    f2h_kernel<<<nTok4 / 256, 256>>>((const float4*)kv,  (uint2*)KVh, nTok4);
    f2h_kernel<<<nW4 / 256, 256>>>((const float4*)q_w, (uint2*)Wqh, nW4);
    f2h_kernel<<<nW4 / 256, 256>>>((const float4*)k_w, (uint2*)Wkh, nW4);
    f2h_kernel<<<nW4 / 256, 256>>>((const float4*)v_w, (uint2*)Wvh, nW4);
    f2h_kernel<<<nW4 / 256, 256>>>((const float4*)o_w, (uint2*)Woh, nW4);

    cudaFuncSetAttribute(gemm_f16, cudaFuncAttributeMaxDynamicSharedMemorySize,
                         GEMM_SMEM);

    const float qsc = 0.125f * 1.44269504088896f;   // SCALE * log2(e)
    dim3 gGrid(NQ / BM, DIM / BN);  // 32 x 8
    gemm_f16<<<gGrid, 256, GEMM_SMEM>>>(Xh,  Wqh, q_b, Qh, NQ,  DIM, DIM, qsc, 1);
    gemm_f16<<<gGrid, 256, GEMM_SMEM>>>(KVh, Wkh, k_b, Kh, NKV, DIM, DIM, 1.f, 1);
    gemm_f16<<<gGrid, 256, GEMM_SMEM>>>(KVh, Wvh, v_b, Vh, NKV, DIM, DIM, 1.f, 1);

    const size_t attnSmem = (size_t)(2 * KVSZH + 128 * PPH) * sizeof(__half); // 55296
    cudaFuncSetAttribute(attn_f16, cudaFuncAttributeMaxDynamicSharedMemorySize,
                         (int)attnSmem);
    dim3 aGrid(NQ / 128, NH);       // 32 x 16
    attn_f16<<<aGrid, 128, attnSmem>>>(Qh, Kh, Vh, AOh);

    gemm_f16<<<gGrid, 256, GEMM_SMEM>>>(AOh, Woh, o_b, out, NQ, DIM, DIM, 1.f, 0);
}

// round 14
// speedup vs baseline: 3.2453x; 1.0703x over previous
#include <cuda_runtime.h>
#include <cuda_fp16.h>
#include <math.h>

#define DIM 1024
#define NQ 4096
#define NKV 4096
#define NH 16
#define HD 64

// ---------------- scratch (device globals; no allocation allowed) ----------
__device__ __half g_Xh[NQ * DIM];
__device__ __half g_KVh[NKV * DIM];
__device__ __half g_Wqh[DIM * DIM];
__device__ __half g_Wkh[DIM * DIM];
__device__ __half g_Wvh[DIM * DIM];
__device__ __half g_Woh[DIM * DIM];
__device__ __half g_Qh[NQ * DIM];
__device__ __half g_Kh[NKV * DIM];
__device__ __half g_Vh[NKV * DIM];
__device__ __half g_AOh[NQ * DIM];

// ---------------- helpers ---------------------------------------------------
__device__ __forceinline__ unsigned saddr(const void* p) {
    return (unsigned)__cvta_generic_to_shared(p);
}
__device__ __forceinline__ void cpa16(unsigned dst, const void* src) {
    asm volatile("cp.async.cg.shared.global [%0], [%1], 16;" :: "r"(dst), "l"(src));
}
__device__ __forceinline__ void cpa_commit() {
    asm volatile("cp.async.commit_group;");
}
template <int N> __device__ __forceinline__ void cpa_wait() {
    asm volatile("cp.async.wait_group %0;" :: "n"(N));
}

__device__ __forceinline__ void mma_f16(float c[4],
                                        unsigned a0, unsigned a1, unsigned a2, unsigned a3,
                                        unsigned b0, unsigned b1) {
    asm volatile(
        "mma.sync.aligned.m16n8k16.row.col.f32.f16.f16.f32 "
        "{%0,%1,%2,%3},{%4,%5,%6,%7},{%8,%9},{%0,%1,%2,%3};"
        : "+f"(c[0]), "+f"(c[1]), "+f"(c[2]), "+f"(c[3])
        : "r"(a0), "r"(a1), "r"(a2), "r"(a3), "r"(b0), "r"(b1));
}

__device__ __forceinline__ void ldsm4(unsigned& r0, unsigned& r1,
                                      unsigned& r2, unsigned& r3, unsigned addr) {
    asm volatile("ldmatrix.sync.aligned.m8n8.x4.shared.b16 {%0,%1,%2,%3}, [%4];"
                 : "=r"(r0), "=r"(r1), "=r"(r2), "=r"(r3) : "r"(addr));
}
__device__ __forceinline__ void ldsm4t(unsigned& r0, unsigned& r1,
                                       unsigned& r2, unsigned& r3, unsigned addr) {
    asm volatile("ldmatrix.sync.aligned.m8n8.x4.trans.shared.b16 {%0,%1,%2,%3}, [%4];"
                 : "=r"(r0), "=r"(r1), "=r"(r2), "=r"(r3) : "r"(addr));
}

__device__ __forceinline__ unsigned lduh(const __half* p) {
    return *reinterpret_cast<const unsigned*>(p);
}

// ---------------- pre-pass: float -> half ----------------------------------
__global__ __launch_bounds__(256)
void f2h_kernel(const float4* __restrict__ src, uint2* __restrict__ dst, int n4) {
    int i = blockIdx.x * blockDim.x + threadIdx.x;
    if (i < n4) {
        float4 v = src[i];
        __half2 h0 = __floats2half2_rn(v.x, v.y);
        __half2 h1 = __floats2half2_rn(v.z, v.w);
        uint2 o;
        o.x = *reinterpret_cast<unsigned*>(&h0);
        o.y = *reinterpret_cast<unsigned*>(&h1);
        dst[i] = o;
    }
}

// ---------------- GEMM (fp16 mma): C[M,N] = X @ W^T + b --------------------
// 128x128x32 tiles, 256 threads (8 warps 4x2), warp tile 32x64, k-step 16.
#define BM 128
#define BN 128
#define BK 32
#define GPH 40   // smem row width in halves (80B, stride 20 words)

#define GEMM_SMEM ((2 * BM * GPH + 2 * BN * GPH) * 2)

__global__ __launch_bounds__(256, 2)
void gemm_f16(const __half* __restrict__ X, const __half* __restrict__ W,
              const float* __restrict__ bias, void* __restrict__ Cout,
              int M, int N, int K, float outScale, int outHalf) {
    extern __shared__ __half gsh[];
    __half* Xs0 = gsh;                               // [2][BM][GPH]
    __half* Ws0 = gsh + 2 * BM * GPH;                // [2][BN][GPH]

    const int tid = threadIdx.x;
    const int warp = tid >> 5, lane = tid & 31;
    const int g = lane >> 2, q = lane & 3;
    const int lm = lane >> 3, lr = lane & 7;
    const int wm = warp >> 1, wn = warp & 1;
    const int rowBase = blockIdx.x * BM;
    const int colBase = blockIdx.y * BN;
    const int NT = K / BK;

    float acc[2][8][4];
    #pragma unroll
    for (int i = 0; i < 2; i++)
        #pragma unroll
        for (int j = 0; j < 8; j++)
            #pragma unroll
            for (int v = 0; v < 4; v++) acc[i][j][v] = 0.f;

    // prologue: tile 0 -> buffer 0
    {
        #pragma unroll
        for (int i = 0; i < 2; i++) {
            int idx = tid + i * 256;          // 0..511
            int r = idx >> 2, c = idx & 3;
            cpa16(saddr(&Xs0[r * GPH + c * 8]), &X[(size_t)(rowBase + r) * K + c * 8]);
            cpa16(saddr(&Ws0[r * GPH + c * 8]), &W[(size_t)(colBase + r) * K + c * 8]);
        }
        cpa_commit();
    }

    for (int kt = 0; kt < NT; kt++) {
        __syncthreads();
        if (kt + 1 < NT) {
            int k0 = (kt + 1) * BK;
            int buf = (kt + 1) & 1;
            __half* Xb = Xs0 + buf * BM * GPH;
            __half* Wb = Ws0 + buf * BN * GPH;
            #pragma unroll
            for (int i = 0; i < 2; i++) {
                int idx = tid + i * 256;
                int r = idx >> 2, c = idx & 3;
                cpa16(saddr(&Xb[r * GPH + c * 8]), &X[(size_t)(rowBase + r) * K + k0 + c * 8]);
                cpa16(saddr(&Wb[r * GPH + c * 8]), &W[(size_t)(colBase + r) * K + k0 + c * 8]);
            }
            cpa_commit();
            cpa_wait<1>();
        } else {
            cpa_wait<0>();
        }
        __syncthreads();

        const __half* Xs = Xs0 + (kt & 1) * BM * GPH;
        const __half* Ws = Ws0 + (kt & 1) * BN * GPH;

        #pragma unroll
        for (int ks = 0; ks < 2; ks++) {          // two k16 steps per BK=32
            const int kh = ks * 16;
            // B fragments via ldmatrix.x4 non-trans:
            // matrices: (j=2jj,klo),(2jj,khi),(2jj+1,klo),(2jj+1,khi)
            unsigned b0[8], b1[8];
            #pragma unroll
            for (int jj = 0; jj < 4; jj++) {
                int jrow = wn * 64 + (2 * jj + (lm >> 1)) * 8 + lr;
                ldsm4(b0[2 * jj], b1[2 * jj], b0[2 * jj + 1], b1[2 * jj + 1],
                      saddr(&Ws[jrow * GPH + kh + 8 * (lm & 1)]));
            }
            #pragma unroll
            for (int i = 0; i < 2; i++) {
                // A fragments: m0 rows0-7 klo, m1 rows8-15 klo, m2 rows0-7 khi, m3 rows8-15 khi
                int arow = wm * 32 + i * 16 + (lm & 1) * 8 + lr;
                unsigned a0, a1, a2, a3;
                ldsm4(a0, a1, a2, a3, saddr(&Xs[arow * GPH + kh + 8 * (lm >> 1)]));
                #pragma unroll
                for (int j = 0; j < 8; j++)
                    mma_f16(acc[i][j], a0, a1, a2, a3, b0[j], b1[j]);
            }
        }
    }

    // epilogue
    #pragma unroll
    for (int i = 0; i < 2; i++) {
        int r0 = rowBase + wm * 32 + i * 16 + g;
        #pragma unroll
        for (int j = 0; j < 8; j++) {
            int col = colBase + wn * 64 + j * 8 + 2 * q;
            float2 bb = *reinterpret_cast<const float2*>(&bias[col]);
            float c00 = (acc[i][j][0] + bb.x) * outScale;
            float c01 = (acc[i][j][1] + bb.y) * outScale;
            float c10 = (acc[i][j][2] + bb.x) * outScale;
            float c11 = (acc[i][j][3] + bb.y) * outScale;
            if (outHalf) {
                __half* Ch = (__half*)Cout;
                *reinterpret_cast<__half2*>(&Ch[(size_t)r0 * N + col]) =
                    __floats2half2_rn(c00, c01);
                *reinterpret_cast<__half2*>(&Ch[(size_t)(r0 + 8) * N + col]) =
                    __floats2half2_rn(c10, c11);
            } else {
                float* Cf = (float*)Cout;
                *reinterpret_cast<float2*>(&Cf[(size_t)r0 * N + col]) = make_float2(c00, c01);
                *reinterpret_cast<float2*>(&Cf[(size_t)(r0 + 8) * N + col]) = make_float2(c10, c11);
            }
        }
    }
}

// ---------------- Flash attention (fp16 mma, ldmatrix everywhere) ----------
// grid (NQ/128, NH), 128 threads (4 warps). Warp w owns q rows 32w..32w+31.
#define KPH 72   // K/V smem row width in halves (144B)
#define PPH 72   // P slab row width in halves
#define KVSZH (64 * KPH + 64 * KPH)   // halves per K+V buffer

__global__ __launch_bounds__(128, 2)
void attn_f16(const __half* __restrict__ Q, const __half* __restrict__ K,
              const __half* __restrict__ V, __half* __restrict__ AO) {
    extern __shared__ __half smh[];
    __half* Ps = smh + 2 * KVSZH;          // 128 x 72 halves

    const int tid = threadIdx.x;
    const int warp = tid >> 5, lane = tid & 31;
    const int g = lane >> 2, q = lane & 3;
    const int lm = lane >> 3, lr = lane & 7;
    const int h = blockIdx.y;
    const int q0 = blockIdx.x * 128;
    const int colBase = h * HD;
    const int NT = NKV / 64;

    // hoist Q fragments (scale pre-folded at Q-projection epilogue)
    unsigned qa[4][4], qc[4][4];
    {
        const __half* Qr0 = Q + (size_t)(q0 + warp * 32 + g) * DIM + colBase;
        const __half* Qr1 = Qr0 + (size_t)8 * DIM;
        const __half* Qr2 = Qr0 + (size_t)16 * DIM;
        const __half* Qr3 = Qr0 + (size_t)24 * DIM;
        #pragma unroll
        for (int s = 0; s < 4; s++) {
            qa[s][0] = lduh(&Qr0[16 * s + 2 * q]);
            qa[s][1] = lduh(&Qr1[16 * s + 2 * q]);
            qa[s][2] = lduh(&Qr0[16 * s + 2 * q + 8]);
            qa[s][3] = lduh(&Qr1[16 * s + 2 * q + 8]);
            qc[s][0] = lduh(&Qr2[16 * s + 2 * q]);
            qc[s][1] = lduh(&Qr3[16 * s + 2 * q]);
            qc[s][2] = lduh(&Qr2[16 * s + 2 * q + 8]);
            qc[s][3] = lduh(&Qr3[16 * s + 2 * q + 8]);
        }
    }

    float oA[8][4], oB[8][4];
    #pragma unroll
    for (int j = 0; j < 8; j++)
        #pragma unroll
        for (int v = 0; v < 4; v++) { oA[j][v] = 0.f; oB[j][v] = 0.f; }
    float l0 = 0.f, l1 = 0.f, l2 = 0.f, l3 = 0.f;

    __half* Pw = Ps + warp * 32 * PPH;

    // prologue: stage tile 0 into buffer 0
    {
        #pragma unroll
        for (int i = 0; i < 4; i++) {
            int idx = tid + i * 128;        // 0..511
            int r = idx >> 3, c = idx & 7;
            cpa16(saddr(&smh[r * KPH + c * 8]), &K[(size_t)r * DIM + colBase + c * 8]);
            cpa16(saddr(&smh[64 * KPH + r * KPH + c * 8]), &V[(size_t)r * DIM + colBase + c * 8]);
        }
        cpa_commit();
    }

    for (int kt = 0; kt < NT; kt++) {
        __syncthreads();
        if (kt + 1 < NT) {
            int kv0 = (kt + 1) * 64;
            __half* Kb = smh + ((kt + 1) & 1) * KVSZH;
            __half* Vb = Kb + 64 * KPH;
            #pragma unroll
            for (int i = 0; i < 4; i++) {
                int idx = tid + i * 128;
                int r = idx >> 3, c = idx & 7;
                cpa16(saddr(&Kb[r * KPH + c * 8]), &K[(size_t)(kv0 + r) * DIM + colBase + c * 8]);
                cpa16(saddr(&Vb[r * KPH + c * 8]), &V[(size_t)(kv0 + r) * DIM + colBase + c * 8]);
            }
            cpa_commit();
            cpa_wait<1>();
        } else {
            cpa_wait<0>();
        }
        __syncthreads();

        const __half* Ks = smh + (kt & 1) * KVSZH;
        const __half* Vs = Ks + 64 * KPH;

        // ---- S = Q @ K^T (K B-frags via ldmatrix.x4 non-trans) ------------
        float sA[8][4], sB[8][4];
        #pragma unroll
        for (int j = 0; j < 8; j++)
            #pragma unroll
            for (int v = 0; v < 4; v++) { sA[j][v] = 0.f; sB[j][v] = 0.f; }
        #pragma unroll
        for (int s = 0; s < 4; s++) {
            unsigned b0[8], b1[8];
            #pragma unroll
            for (int jj = 0; jj < 4; jj++) {
                int krow = (2 * jj + (lm >> 1)) * 8 + lr;
                ldsm4(b0[2 * jj], b1[2 * jj], b0[2 * jj + 1], b1[2 * jj + 1],
                      saddr(&Ks[krow * KPH + 16 * s + 8 * (lm & 1)]));
            }
            #pragma unroll
            for (int j = 0; j < 8; j++) {
                mma_f16(sA[j], qa[s][0], qa[s][1], qa[s][2], qa[s][3], b0[j], b1[j]);
                mma_f16(sB[j], qc[s][0], qc[s][1], qc[s][2], qc[s][3], b0[j], b1[j]);
            }
        }

        // ---- shift-free softmax: p = exp2(s) ------------------------------
        #pragma unroll
        for (int j = 0; j < 8; j++) {
            float p0 = exp2f(sA[j][0]);
            float p1 = exp2f(sA[j][1]);
            float p2 = exp2f(sA[j][2]);
            float p3 = exp2f(sA[j][3]);
            sA[j][0] = p0; sA[j][1] = p1; sA[j][2] = p2; sA[j][3] = p3;
            l0 += p0 + p1; l1 += p2 + p3;
            float r0v = exp2f(sB[j][0]);
            float r1v = exp2f(sB[j][1]);
            float r2v = exp2f(sB[j][2]);
            float r3v = exp2f(sB[j][3]);
            sB[j][0] = r0v; sB[j][1] = r1v; sB[j][2] = r2v; sB[j][3] = r3v;
            l2 += r0v + r1v; l3 += r2v + r3v;
        }

        // ---- P -> per-warp smem slab (half2) ------------------------------
        #pragma unroll
        for (int j = 0; j < 8; j++) {
            int col = 8 * j + 2 * q;
            *reinterpret_cast<__half2*>(&Pw[g * PPH + col]) =
                __floats2half2_rn(sA[j][0], sA[j][1]);
            *reinterpret_cast<__half2*>(&Pw[(g + 8) * PPH + col]) =
                __floats2half2_rn(sA[j][2], sA[j][3]);
            *reinterpret_cast<__half2*>(&Pw[(g + 16) * PPH + col]) =
                __floats2half2_rn(sB[j][0], sB[j][1]);
            *reinterpret_cast<__half2*>(&Pw[(g + 24) * PPH + col]) =
                __floats2half2_rn(sB[j][2], sB[j][3]);
        }
        __syncwarp();

        // ---- O += P @ V (P A-frags + V B-frags via ldmatrix) --------------
        #pragma unroll
        for (int s = 0; s < 4; s++) {
            unsigned a0, a1, a2, a3, c0, c1, c2, c3;
            {
                int prow = (lm & 1) * 8 + lr;
                ldsm4(a0, a1, a2, a3,
                      saddr(&Pw[prow * PPH + 16 * s + 8 * (lm >> 1)]));
                ldsm4(c0, c1, c2, c3,
                      saddr(&Pw[(16 + prow) * PPH + 16 * s + 8 * (lm >> 1)]));
            }
            #pragma unroll
            for (int jj = 0; jj < 4; jj++) {
                int kvrow = 16 * s + 8 * (lm & 1) + lr;
                int ncol = 16 * jj + 8 * (lm >> 1);
                unsigned vb0, vb1, vb2, vb3;
                ldsm4t(vb0, vb1, vb2, vb3, saddr(&Vs[kvrow * KPH + ncol]));
                mma_f16(oA[2 * jj + 0], a0, a1, a2, a3, vb0, vb1);
                mma_f16(oA[2 * jj + 1], a0, a1, a2, a3, vb2, vb3);
                mma_f16(oB[2 * jj + 0], c0, c1, c2, c3, vb0, vb1);
                mma_f16(oB[2 * jj + 1], c0, c1, c2, c3, vb2, vb3);
            }
        }
    }

    // final l reduction, normalize + write (half2, feeds O-proj GEMM)
    #pragma unroll
    for (int msk = 1; msk < 4; msk <<= 1) {
        l0 += __shfl_xor_sync(0xffffffffu, l0, msk);
        l1 += __shfl_xor_sync(0xffffffffu, l1, msk);
        l2 += __shfl_xor_sync(0xffffffffu, l2, msk);
        l3 += __shfl_xor_sync(0xffffffffu, l3, msk);
    }
    float inv0 = 1.f / l0, inv1 = 1.f / l1, inv2 = 1.f / l2, inv3 = 1.f / l3;
    int r0 = q0 + warp * 32 + g;
    #pragma unroll
    for (int j = 0; j < 8; j++) {
        int col = colBase + 8 * j + 2 * q;
        *reinterpret_cast<__half2*>(&AO[(size_t)r0 * DIM + col]) =
            __floats2half2_rn(oA[j][0] * inv0, oA[j][1] * inv0);
        *reinterpret_cast<__half2*>(&AO[(size_t)(r0 + 8) * DIM + col]) =
            __floats2half2_rn(oA[j][2] * inv1, oA[j][3] * inv1);
        *reinterpret_cast<__half2*>(&AO[(size_t)(r0 + 16) * DIM + col]) =
            __floats2half2_rn(oB[j][0] * inv2, oB[j][1] * inv2);
        *reinterpret_cast<__half2*>(&AO[(size_t)(r0 + 24) * DIM + col]) =
            __floats2half2_rn(oB[j][2] * inv3, oB[j][3] * inv3);
    }
}

// ---------------- launch ---------------------------------------------------
extern "C" void kernel_launch(void* const* d_in, const int* in_sizes, int n_in,
                              void* d_out, int out_size) {
    const float* q   = (const float*)d_in[0];
    const float* kv  = (const float*)d_in[1];
    const float* q_w = (const float*)d_in[2];
    const float* q_b = (const float*)d_in[3];
    const float* k_w = (const float*)d_in[4];
    const float* k_b = (const float*)d_in[5];
    const float* v_w = (const float*)d_in[6];
    const float* v_b = (const float*)d_in[7];
    const float* o_w = (const float*)d_in[8];
    const float* o_b = (const float*)d_in[9];
    float* out = (float*)d_out;

    __half *Xh, *KVh, *Wqh, *Wkh, *Wvh, *Woh, *Qh, *Kh, *Vh, *AOh;
    cudaGetSymbolAddress((void**)&Xh,  g_Xh);
    cudaGetSymbolAddress((void**)&KVh, g_KVh);
    cudaGetSymbolAddress((void**)&Wqh, g_Wqh);
    cudaGetSymbolAddress((void**)&Wkh, g_Wkh);
    cudaGetSymbolAddress((void**)&Wvh, g_Wvh);
    cudaGetSymbolAddress((void**)&Woh, g_Woh);
    cudaGetSymbolAddress((void**)&Qh,  g_Qh);
    cudaGetSymbolAddress((void**)&Kh,  g_Kh);
    cudaGetSymbolAddress((void**)&Vh,  g_Vh);
    cudaGetSymbolAddress((void**)&AOh, g_AOh);

    // pre-convert inputs + weights to fp16
    const int nTok4 = NQ * DIM / 4;
    const int nW4   = DIM * DIM / 4;
    f2h_kernel<<<nTok4 / 256, 256>>>((const float4*)q,   (uint2*)Xh,  nTok4);
    f2h_kernel<<<nTok4 / 256, 256>>>((const float4*)kv,  (uint2*)KVh, nTok4);
    f2h_kernel<<<nW4 / 256, 256>>>((const float4*)q_w, (uint2*)Wqh, nW4);
    f2h_kernel<<<nW4 / 256, 256>>>((const float4*)k_w, (uint2*)Wkh, nW4);
    f2h_kernel<<<nW4 / 256, 256>>>((const float4*)v_w, (uint2*)Wvh, nW4);
    f2h_kernel<<<nW4 / 256, 256>>>((const float4*)o_w, (uint2*)Woh, nW4);

    cudaFuncSetAttribute(gemm_f16, cudaFuncAttributeMaxDynamicSharedMemorySize,
                         GEMM_SMEM);

    const float qsc = 0.125f * 1.44269504088896f;   // SCALE * log2(e)
    dim3 gGrid(NQ / BM, DIM / BN);  // 32 x 8
    gemm_f16<<<gGrid, 256, GEMM_SMEM>>>(Xh,  Wqh, q_b, Qh, NQ,  DIM, DIM, qsc, 1);
    gemm_f16<<<gGrid, 256, GEMM_SMEM>>>(KVh, Wkh, k_b, Kh, NKV, DIM, DIM, 1.f, 1);
    gemm_f16<<<gGrid, 256, GEMM_SMEM>>>(KVh, Wvh, v_b, Vh, NKV, DIM, DIM, 1.f, 1);

    const size_t attnSmem = (size_t)(2 * KVSZH + 128 * PPH) * sizeof(__half); // 55296
    cudaFuncSetAttribute(attn_f16, cudaFuncAttributeMaxDynamicSharedMemorySize,
                         (int)attnSmem);
    dim3 aGrid(NQ / 128, NH);       // 32 x 16
    attn_f16<<<aGrid, 128, attnSmem>>>(Qh, Kh, Vh, AOh);

    gemm_f16<<<gGrid, 256, GEMM_SMEM>>>(AOh, Woh, o_b, out, NQ, DIM, DIM, 1.f, 0);
}